// round 9
// baseline (speedup 1.0000x reference)
#include <cuda_runtime.h>
#include <cuda_fp16.h>
#include <math.h>
#include <stdint.h>

#define CBATCH   4
#define CSEQ     2048
#define CDMODEL  1024
#define CDMAMBA  2048
#define CDSTATE  16
#define CNHEADS  32
#define CMROWS   (CBATCH * CSEQ)          // 8192
#define CNCHUNK  32
#define CLCHUNK  (CSEQ / CNCHUNK)         // 64
#define CHEADDIM (CDMAMBA / CNHEADS)      // 64
#define CHALF    (CDMAMBA / 2)            // 1024

typedef unsigned short ushort_t;

// ---------------- scratch (static device arrays; no runtime allocation) ----------------
__device__ float g_Bn  [CMROWS * CDSTATE];
__device__ float g_Cn  [CMROWS * CDSTATE];
__device__ float g_hloc [CBATCH * CNCHUNK * CDSTATE * CDMAMBA];
__device__ float g_hinit[CBATCH * CNCHUNK * CDSTATE * CDMAMBA];
__device__ float g_S    [CBATCH * CNCHUNK * CDMAMBA];

// fp16 operands / intermediates
__device__ ushort_t g_xn_h[CMROWS * CDMODEL];
__device__ ushort_t g_w1_h[CDMAMBA * CDMODEL];
__device__ ushort_t g_w2_h[CDMAMBA * CDMODEL];
__device__ ushort_t g_w3_h[CDMAMBA * CDMAMBA];
__device__ ushort_t g_x16 [CMROWS * CDMAMBA];   // x_ssm fp16
__device__ ushort_t g_dt16[CMROWS * CDMAMBA];   // dt fp16
__device__ ushort_t g_y_h [CMROWS * CDMAMBA];   // y fp16

// ---------------- PTX helpers (baseline sm_80-level features only) ----------------
__device__ __forceinline__ uint32_t smem_u32(const void* p) {
    uint32_t a;
    asm("{ .reg .u64 t; cvta.to.shared.u64 t, %1; cvt.u32.u64 %0, t; }" : "=r"(a) : "l"(p));
    return a;
}

#define CP_ASYNC16(dst, src) \
    asm volatile("cp.async.cg.shared.global [%0], [%1], 16;" :: "r"(dst), "l"(src))
#define CP_COMMIT() asm volatile("cp.async.commit_group;" ::: "memory")
#define CP_WAIT0() asm volatile("cp.async.wait_group 0;" ::: "memory")
#define CP_WAIT1() asm volatile("cp.async.wait_group 1;" ::: "memory")

#define LDSM4(r, addr) \
    asm volatile("ldmatrix.sync.aligned.m8n8.x4.shared.b16 {%0,%1,%2,%3}, [%4];" \
        : "=r"((r)[0]), "=r"((r)[1]), "=r"((r)[2]), "=r"((r)[3]) : "r"(addr))

#define MMA_F16(d, a, b0, b1) \
    asm volatile("mma.sync.aligned.m16n8k16.row.col.f32.f16.f16.f32 " \
        "{%0,%1,%2,%3}, {%4,%5,%6,%7}, {%8,%9}, {%0,%1,%2,%3};" \
        : "+f"((d)[0]), "+f"((d)[1]), "+f"((d)[2]), "+f"((d)[3]) \
        : "r"((a)[0]), "r"((a)[1]), "r"((a)[2]), "r"((a)[3]), "r"(b0), "r"(b1))

__device__ __forceinline__ uint32_t swz(uint32_t off) {   // SW128 xor swizzle
    return off ^ ((off >> 3) & 0x70);
}

// ---------------- fp16 conversion ----------------
__global__ __launch_bounds__(256) void conv_h(const float* __restrict__ in,
                                              ushort_t* __restrict__ hi, int n4) {
    int i = blockIdx.x * 256 + threadIdx.x;
    if (i >= n4) return;
    float4 v = reinterpret_cast<const float4*>(in)[i];
    ushort4 h;
    h.x = __half_as_ushort(__float2half(v.x));
    h.y = __half_as_ushort(__float2half(v.y));
    h.z = __half_as_ushort(__float2half(v.z));
    h.w = __half_as_ushort(__float2half(v.w));
    reinterpret_cast<ushort4*>(hi)[i] = h;
}

__device__ __forceinline__ float dt_transform(float v, float b) {
    v += b;
    v = fminf(fmaxf(v, -10.0f), 5.0f);
    v = log1pf(expf(v));
    return fminf(fmaxf(v, 1e-4f), 0.1f);
}

// ---------------- HMMA fp16 GEMM: 64x64 warp tiles, 128-thread CTA ----------------
// C[m,n] = sum_k A[m,k]*W[n,k]; CTA tile 128x128, BK=64, 4 warps (2x2), 64x64 warp tiles.
// 3 stages x 32KB = 96KB/CTA, 2 CTA/SM, one __syncthreads per K-chunk.
// MMA:LDSM per k16 = 32:8 = 4.
#define TILE_B   16384
#define STAGE_B  32768
#define SM_TOTAL (3 * STAGE_B)   // 98304
#define GTHR     128

__device__ __forceinline__ void stage_load(
    const ushort_t* __restrict__ Ah, const ushort_t* __restrict__ Wh,
    uint32_t sbase, int m0, int n0, int kc, int K, int tid) {
#pragma unroll
    for (int tile = 0; tile < 2; tile++) {
        const ushort_t* g = (tile == 0) ? Ah : Wh;
        int row0 = (tile == 0) ? m0 : n0;
#pragma unroll
        for (int j = 0; j < 8; j++) {
            int idx = tid + j * GTHR;          // 0..1023
            int row = idx >> 3, seg = idx & 7;
            const ushort_t* src = g + (size_t)(row0 + row) * K + kc + seg * 8;
            uint32_t dst = sbase + tile * TILE_B + swz((uint32_t)(row * 128 + seg * 16));
            CP_ASYNC16(dst, src);
        }
    }
}

__device__ __forceinline__ void stage_compute(uint32_t sbase, int wm, int wn,
                                              int lane, float acc[4][8][4]) {
    const uint32_t aA = sbase;
    const uint32_t aW = sbase + TILE_B;
    const int arow = wm + (lane & 15);
    const int akb  = (lane >> 4) * 16;
    const int brow = wn + ((lane >> 4) << 3) + (lane & 7);
    const int bkb  = ((lane >> 3) & 1) * 16;

#pragma unroll
    for (int ks = 0; ks < 4; ks++) {
        const int kb = ks * 32;
        uint32_t ah[4][4];
#pragma unroll
        for (int mi = 0; mi < 4; mi++) {
            uint32_t off = swz((uint32_t)((arow + mi * 16) * 128 + akb + kb));
            LDSM4(ah[mi], aA + off);
        }
        uint32_t bh[4][4];
#pragma unroll
        for (int ni = 0; ni < 4; ni++) {
            uint32_t off = swz((uint32_t)((brow + ni * 16) * 128 + bkb + kb));
            LDSM4(bh[ni], aW + off);
        }
#pragma unroll
        for (int mi = 0; mi < 4; mi++) {
#pragma unroll
            for (int ni = 0; ni < 4; ni++) {
                MMA_F16(acc[mi][2 * ni + 0], ah[mi], bh[ni][0], bh[ni][1]);
                MMA_F16(acc[mi][2 * ni + 1], ah[mi], bh[ni][2], bh[ni][3]);
            }
        }
    }
}

// OUT16=true : blocks < n1blk write C1h = fp16(A*W1^T); blocks >= n1blk write
//              C2h = fp16(dt_transform(A*W2^T + bias)).
// OUT16=false: all blocks write Cf (fp32) = A*W1^T.
template <bool OUT16>
__global__ __launch_bounds__(GTHR, 2) void gemm_mma(
    const ushort_t* __restrict__ Ah,
    const ushort_t* __restrict__ W1, const ushort_t* __restrict__ W2,
    const float* __restrict__ bias,
    ushort_t* __restrict__ C1h, ushort_t* __restrict__ C2h, float* __restrict__ Cf,
    int n1blk, int N, int K) {
    extern __shared__ __align__(1024) char smem[];
    const uint32_t sb = smem_u32(smem);
    const int tid = threadIdx.x, lane = tid & 31, w = tid >> 5;
    const int m0 = blockIdx.y * 128;
    const bool second = ((int)blockIdx.x >= n1blk);
    const int n0 = (second ? (int)blockIdx.x - n1blk : (int)blockIdx.x) * 128;
    const ushort_t* Wh = second ? W2 : W1;
    const int wm = (w & 1) * 64, wn = (w >> 1) * 64;
    const int NC = K >> 6;

    float acc[4][8][4];
#pragma unroll
    for (int i = 0; i < 4; i++)
#pragma unroll
        for (int j = 0; j < 8; j++)
#pragma unroll
            for (int q = 0; q < 4; q++) acc[i][j][q] = 0.0f;

    stage_load(Ah, Wh, sb + 0 * STAGE_B, m0, n0, 0, K, tid);  CP_COMMIT();
    stage_load(Ah, Wh, sb + 1 * STAGE_B, m0, n0, 64, K, tid); CP_COMMIT();

    int sc = 0, sl = 2;
    for (int c = 0; c < NC; c++) {
        if (c + 1 < NC) { CP_WAIT1(); } else { CP_WAIT0(); }
        __syncthreads();
        // load buffer sl == buffer consumed at iter c-1; all warps are past it (sync above)
        if (c + 2 < NC) {
            stage_load(Ah, Wh, sb + sl * STAGE_B, m0, n0, (c + 2) * 64, K, tid);
            CP_COMMIT();
            sl = (sl == 2) ? 0 : sl + 1;
        }
        stage_compute(sb + sc * STAGE_B, wm, wn, lane, acc);
        sc = (sc == 2) ? 0 : sc + 1;
    }

    // epilogue
    const int gm = m0 + wm, gn = n0 + wn;
    const int r = lane >> 2, cp = (lane & 3) * 2;
#pragma unroll
    for (int mi = 0; mi < 4; mi++) {
#pragma unroll
        for (int nj = 0; nj < 8; nj++) {
            int row = gm + mi * 16 + r;
            int col = gn + nj * 8 + cp;
            float v0 = acc[mi][nj][0], v1 = acc[mi][nj][1];
            float v2 = acc[mi][nj][2], v3 = acc[mi][nj][3];
            if (OUT16) {
                if (second) {
                    float2 bb = *reinterpret_cast<const float2*>(&bias[col]);
                    v0 = dt_transform(v0, bb.x);
                    v1 = dt_transform(v1, bb.y);
                    v2 = dt_transform(v2, bb.x);
                    v3 = dt_transform(v3, bb.y);
                }
                ushort_t* C = second ? C2h : C1h;
                __half2 h01 = __halves2half2(__float2half(v0), __float2half(v1));
                __half2 h23 = __halves2half2(__float2half(v2), __float2half(v3));
                *reinterpret_cast<__half2*>(&C[(size_t)row * N + col]) = h01;
                *reinterpret_cast<__half2*>(&C[(size_t)(row + 8) * N + col]) = h23;
            } else {
                *reinterpret_cast<float2*>(&Cf[(size_t)row * N + col]) = make_float2(v0, v1);
                *reinterpret_cast<float2*>(&Cf[(size_t)(row + 8) * N + col]) = make_float2(v2, v3);
            }
        }
    }
}

// ---------------- B/C projection + row normalization ----------------
__global__ __launch_bounds__(128) void bc_kernel(const float* __restrict__ X,
                                                 const float* __restrict__ WB,
                                                 const float* __restrict__ WC) {
    int warp = threadIdx.x >> 5;
    int lane = threadIdx.x & 31;
    int m = blockIdx.x * 4 + warp;
    const float* Wr = (lane < 16) ? (WB + (size_t)lane * CDMODEL)
                                  : (WC + (size_t)(lane - 16) * CDMODEL);
    const float* Xr = X + (size_t)m * CDMODEL;

    float4 av = make_float4(0.f, 0.f, 0.f, 0.f);
    for (int k = 0; k < CDMODEL; k += 4) {
        float4 xv = *reinterpret_cast<const float4*>(&Xr[k]);
        float4 wv = *reinterpret_cast<const float4*>(&Wr[k]);
        av.x = fmaf(xv.x, wv.x, av.x);
        av.y = fmaf(xv.y, wv.y, av.y);
        av.z = fmaf(xv.z, wv.z, av.z);
        av.w = fmaf(xv.w, wv.w, av.w);
    }
    float acc = (av.x + av.y) + (av.z + av.w);

    float ss = acc * acc;
#pragma unroll
    for (int off = 8; off >= 1; off >>= 1)
        ss += __shfl_xor_sync(0xffffffffu, ss, off);
    float scale = 1.0f / fmaxf(sqrtf(ss), 1.0f);
    float v = acc * scale;
    if (lane < 16) g_Bn[(size_t)m * 16 + lane] = v;
    else           g_Cn[(size_t)m * 16 + (lane - 16)] = v;
}

__device__ __forceinline__ void load16(const float* p, float* v) {
    const float4* q = reinterpret_cast<const float4*>(p);
    float4 a = q[0], b = q[1], c = q[2], d = q[3];
    v[0] = a.x; v[1] = a.y; v[2] = a.z; v[3] = a.w;
    v[4] = b.x; v[5] = b.y; v[6] = b.z; v[7] = b.w;
    v[8] = c.x; v[9] = c.y; v[10] = c.z; v[11] = c.w;
    v[12] = d.x; v[13] = d.y; v[14] = d.z; v[15] = d.w;
}

__device__ __forceinline__ bool load_A(const float* __restrict__ A_log, int d, float* Av) {
    int head = d / CHEADDIM;
    bool fast = true;
#pragma unroll
    for (int n = 0; n < 16; n++) {
        Av[n] = expf(A_log[head * 16 + n]);
        if (fabsf(Av[n] - (float)(n + 1)) > 1e-3f * (float)(n + 1)) fast = false;
    }
    return fast;
}

__device__ __forceinline__ float ldh(const ushort_t* p) {
    return __half2float(__ushort_as_half(*p));
}

// ---------------- scan pass 1: 2 channels/thread (d and d+1024) ----------------
__global__ __launch_bounds__(256) void scan_pass1(const float* __restrict__ A_log) {
    int d0 = blockIdx.x * 256 + threadIdx.x;   // 0..1023
    int d1 = d0 + CHALF;
    int c = blockIdx.y;
    int b = blockIdx.z;

    float Av0[16], Av1[16];
    bool fastA = load_A(A_log, d0, Av0) && load_A(A_log, d1, Av1);

    float h0[16], h1[16];
#pragma unroll
    for (int n = 0; n < 16; n++) { h0[n] = 0.0f; h1[n] = 0.0f; }
    float S0 = 0.0f, S1 = 0.0f;

    int row0 = b * CSEQ + c * CLCHUNK;
    for (int t = 0; t < CLCHUNK; t++) {
        size_t ro = (size_t)(row0 + t) * CDMAMBA + d0;
        float dt0 = ldh(&g_dt16[ro]),         x0 = ldh(&g_x16[ro]);
        float dt1 = ldh(&g_dt16[ro + CHALF]), x1 = ldh(&g_x16[ro + CHALF]);
        float Bv[16];
        load16(g_Bn + (size_t)(row0 + t) * 16, Bv);
        S0 += dt0; S1 += dt1;
        float dtx0 = dt0 * x0, dtx1 = dt1 * x1;
        if (fastA) {
            float r0 = __expf(-dt0), p0 = 1.0f;
            float r1 = __expf(-dt1), p1 = 1.0f;
#pragma unroll
            for (int n = 0; n < 16; n++) {
                p0 *= r0; h0[n] = fmaf(p0, h0[n], dtx0 * Bv[n]);
                p1 *= r1; h1[n] = fmaf(p1, h1[n], dtx1 * Bv[n]);
            }
        } else {
#pragma unroll
            for (int n = 0; n < 16; n++) {
                h0[n] = fmaf(__expf(-dt0 * Av0[n]), h0[n], dtx0 * Bv[n]);
                h1[n] = fmaf(__expf(-dt1 * Av1[n]), h1[n], dtx1 * Bv[n]);
            }
        }
    }
    size_t base = ((size_t)(b * CNCHUNK + c) * 16) * CDMAMBA + d0;
#pragma unroll
    for (int n = 0; n < 16; n++) {
        g_hloc[base + (size_t)n * CDMAMBA] = h0[n];
        g_hloc[base + (size_t)n * CDMAMBA + CHALF] = h1[n];
    }
    g_S[(size_t)(b * CNCHUNK + c) * CDMAMBA + d0] = S0;
    g_S[(size_t)(b * CNCHUNK + c) * CDMAMBA + d1] = S1;
}

// ---------------- scan pass 2 ----------------
__global__ __launch_bounds__(256) void scan_pass2(const float* __restrict__ A_log) {
    int idx = blockIdx.x * 256 + threadIdx.x;
    int b = idx / CDMAMBA;
    int d = idx % CDMAMBA;

    float Av[16];
    bool fastA = load_A(A_log, d, Av);

    float h[16];
#pragma unroll
    for (int n = 0; n < 16; n++) h[n] = 0.0f;

    for (int c = 0; c < CNCHUNK; c++) {
        size_t base = ((size_t)(b * CNCHUNK + c) * 16) * CDMAMBA + d;
#pragma unroll
        for (int n = 0; n < 16; n++) g_hinit[base + (size_t)n * CDMAMBA] = h[n];
        float S = g_S[(size_t)(b * CNCHUNK + c) * CDMAMBA + d];
        if (fastA) {
            float R = __expf(-S), p = 1.0f;
#pragma unroll
            for (int n = 0; n < 16; n++) {
                p *= R;
                h[n] = fmaf(p, h[n], g_hloc[base + (size_t)n * CDMAMBA]);
            }
        } else {
#pragma unroll
            for (int n = 0; n < 16; n++) {
                float P = __expf(-S * Av[n]);
                h[n] = fmaf(P, h[n], g_hloc[base + (size_t)n * CDMAMBA]);
            }
        }
    }
}

// ---------------- scan pass 3: 2 channels/thread, emit y as fp16 ----------------
__global__ __launch_bounds__(256) void scan_pass3(const float* __restrict__ A_log,
                                                  const float* __restrict__ Dvec) {
    int d0 = blockIdx.x * 256 + threadIdx.x;   // 0..1023
    int d1 = d0 + CHALF;
    int c = blockIdx.y;
    int b = blockIdx.z;

    float Av0[16], Av1[16];
    bool fastA = load_A(A_log, d0, Av0) && load_A(A_log, d1, Av1);
    float Dd0 = Dvec[d0], Dd1 = Dvec[d1];

    float h0[16], h1[16];
    size_t base = ((size_t)(b * CNCHUNK + c) * 16) * CDMAMBA + d0;
#pragma unroll
    for (int n = 0; n < 16; n++) {
        h0[n] = g_hinit[base + (size_t)n * CDMAMBA];
        h1[n] = g_hinit[base + (size_t)n * CDMAMBA + CHALF];
    }

    int row0 = b * CSEQ + c * CLCHUNK;
    for (int t = 0; t < CLCHUNK; t++) {
        size_t ro = (size_t)(row0 + t) * CDMAMBA + d0;
        float dt0 = ldh(&g_dt16[ro]),         x0 = ldh(&g_x16[ro]);
        float dt1 = ldh(&g_dt16[ro + CHALF]), x1 = ldh(&g_x16[ro + CHALF]);
        float Bv[16], Cv[16];
        load16(g_Bn + (size_t)(row0 + t) * 16, Bv);
        load16(g_Cn + (size_t)(row0 + t) * 16, Cv);
        float dtx0 = dt0 * x0, dtx1 = dt1 * x1;
        float y0 = 0.0f, y1 = 0.0f;
        if (fastA) {
            float r0 = __expf(-dt0), p0 = 1.0f;
            float r1 = __expf(-dt1), p1 = 1.0f;
#pragma unroll
            for (int n = 0; n < 16; n++) {
                p0 *= r0; h0[n] = fmaf(p0, h0[n], dtx0 * Bv[n]); y0 = fmaf(h0[n], Cv[n], y0);
                p1 *= r1; h1[n] = fmaf(p1, h1[n], dtx1 * Bv[n]); y1 = fmaf(h1[n], Cv[n], y1);
            }
        } else {
#pragma unroll
            for (int n = 0; n < 16; n++) {
                h0[n] = fmaf(__expf(-dt0 * Av0[n]), h0[n], dtx0 * Bv[n]); y0 = fmaf(h0[n], Cv[n], y0);
                h1[n] = fmaf(__expf(-dt1 * Av1[n]), h1[n], dtx1 * Bv[n]); y1 = fmaf(h1[n], Cv[n], y1);
            }
        }
        g_y_h[ro]         = __half_as_ushort(__float2half(fmaf(x0, Dd0, y0)));
        g_y_h[ro + CHALF] = __half_as_ushort(__float2half(fmaf(x1, Dd1, y1)));
    }
}

// ---------------- launch ----------------
extern "C" void kernel_launch(void* const* d_in, const int* in_sizes, int n_in,
                              void* d_out, int out_size) {
    (void)in_sizes; (void)n_in; (void)out_size;
    const float* x_norm     = (const float*)d_in[0];
    const float* x_proj_w   = (const float*)d_in[1];
    const float* dt_proj_w  = (const float*)d_in[2];
    const float* dt_proj_b  = (const float*)d_in[3];
    const float* B_proj_w   = (const float*)d_in[4];
    const float* C_proj_w   = (const float*)d_in[5];
    const float* A_log      = (const float*)d_in[6];
    const float* Dvec       = (const float*)d_in[7];
    const float* out_proj_w = (const float*)d_in[8];
    float* out = (float*)d_out;

    void *p_xnh, *p_w1h, *p_w2h, *p_w3h, *p_yh, *p_x16, *p_dt16;
    cudaGetSymbolAddress(&p_xnh, g_xn_h);
    cudaGetSymbolAddress(&p_w1h, g_w1_h);
    cudaGetSymbolAddress(&p_w2h, g_w2_h);
    cudaGetSymbolAddress(&p_w3h, g_w3_h);
    cudaGetSymbolAddress(&p_yh, g_y_h);
    cudaGetSymbolAddress(&p_x16, g_x16);
    cudaGetSymbolAddress(&p_dt16, g_dt16);

    cudaFuncSetAttribute(gemm_mma<true>, cudaFuncAttributeMaxDynamicSharedMemorySize, SM_TOTAL);
    cudaFuncSetAttribute(gemm_mma<false>, cudaFuncAttributeMaxDynamicSharedMemorySize, SM_TOTAL);

    // fp16 conversions
    {
        int n4 = (CMROWS * CDMODEL) / 4;
        conv_h<<<n4 / 256, 256>>>(x_norm, (ushort_t*)p_xnh, n4);
        n4 = (CDMAMBA * CDMODEL) / 4;
        conv_h<<<n4 / 256, 256>>>(x_proj_w, (ushort_t*)p_w1h, n4);
        conv_h<<<n4 / 256, 256>>>(dt_proj_w, (ushort_t*)p_w2h, n4);
        n4 = (CDMAMBA * CDMAMBA) / 4;
        conv_h<<<n4 / 256, 256>>>(out_proj_w, (ushort_t*)p_w3h, n4);
    }

    // 1+2) fused: x16 = fp16(x_norm @ W1^T) ; dt16 = fp16(dt_transform(x_norm @ W2^T + b))
    {
        dim3 grid(2 * (CDMAMBA / 128), CMROWS / 128);   // (32, 64)
        gemm_mma<true><<<grid, GTHR, SM_TOTAL>>>(
            (const ushort_t*)p_xnh,
            (const ushort_t*)p_w1h, (const ushort_t*)p_w2h, dt_proj_b,
            (ushort_t*)p_x16, (ushort_t*)p_dt16, nullptr,
            CDMAMBA / 128, CDMAMBA, CDMODEL);
    }
    // 3) normalized B, C
    bc_kernel<<<CMROWS / 4, 128>>>(x_norm, B_proj_w, C_proj_w);
    // 4-6) chunked selective scan (2 channels per thread in pass1/pass3)
    dim3 scan_grid(CHALF / 256, CNCHUNK, CBATCH);   // (4, 32, 4)
    scan_pass1<<<scan_grid, 256>>>(A_log);
    scan_pass2<<<(CBATCH * CDMAMBA) / 256, 256>>>(A_log);
    scan_pass3<<<scan_grid, 256>>>(A_log, Dvec);
    // 7) out = y @ out_proj_w^T  (fp32 output)
    {
        dim3 grid(CDMAMBA / 128, CMROWS / 128);   // (16, 64)
        gemm_mma<false><<<grid, GTHR, SM_TOTAL>>>(
            (const ushort_t*)p_yh,
            (const ushort_t*)p_w3h, (const ushort_t*)p_w3h, nullptr,
            nullptr, nullptr, out,
            CDMAMBA / 128, CDMAMBA, CDMAMBA);
    }
}

// round 10
// speedup vs baseline: 1.0300x; 1.0300x over previous
#include <cuda_runtime.h>
#include <cuda_fp16.h>
#include <math.h>
#include <stdint.h>

#define CBATCH   4
#define CSEQ     2048
#define CDMODEL  1024
#define CDMAMBA  2048
#define CDSTATE  16
#define CNHEADS  32
#define CMROWS   (CBATCH * CSEQ)          // 8192
#define CNCHUNK  32
#define CLCHUNK  (CSEQ / CNCHUNK)         // 64
#define CHEADDIM (CDMAMBA / CNHEADS)      // 64
#define CHALF    (CDMAMBA / 2)            // 1024

typedef unsigned short ushort_t;

// ---------------- scratch (static device arrays; no runtime allocation) ----------------
__device__ float g_Bn  [CMROWS * CDSTATE];
__device__ float g_Cn  [CMROWS * CDSTATE];
__device__ float g_hloc [CBATCH * CNCHUNK * CDSTATE * CDMAMBA];
__device__ float g_hinit[CBATCH * CNCHUNK * CDSTATE * CDMAMBA];
__device__ float g_S    [CBATCH * CNCHUNK * CDMAMBA];

// fp16 operands / intermediates
__device__ ushort_t g_xn_h[CMROWS * CDMODEL];
__device__ ushort_t g_w1_h[CDMAMBA * CDMODEL];
__device__ ushort_t g_w2_h[CDMAMBA * CDMODEL];
__device__ ushort_t g_w3_h[CDMAMBA * CDMAMBA];
__device__ ushort_t g_x16 [CMROWS * CDMAMBA];   // x_ssm fp16
__device__ ushort_t g_dt16[CMROWS * CDMAMBA];   // dt fp16
__device__ ushort_t g_y_h [CMROWS * CDMAMBA];   // y fp16

// ---------------- PTX helpers (baseline sm_80-level features only) ----------------
__device__ __forceinline__ uint32_t smem_u32(const void* p) {
    uint32_t a;
    asm("{ .reg .u64 t; cvta.to.shared.u64 t, %1; cvt.u32.u64 %0, t; }" : "=r"(a) : "l"(p));
    return a;
}

#define CP_ASYNC16(dst, src) \
    asm volatile("cp.async.cg.shared.global [%0], [%1], 16;" :: "r"(dst), "l"(src))
#define CP_COMMIT() asm volatile("cp.async.commit_group;" ::: "memory")
#define CP_WAIT0() asm volatile("cp.async.wait_group 0;" ::: "memory")
#define CP_WAIT1() asm volatile("cp.async.wait_group 1;" ::: "memory")

#define LDSM4(r, addr) \
    asm volatile("ldmatrix.sync.aligned.m8n8.x4.shared.b16 {%0,%1,%2,%3}, [%4];" \
        : "=r"((r)[0]), "=r"((r)[1]), "=r"((r)[2]), "=r"((r)[3]) : "r"(addr))

#define MMA_F16(d, a, b0, b1) \
    asm volatile("mma.sync.aligned.m16n8k16.row.col.f32.f16.f16.f32 " \
        "{%0,%1,%2,%3}, {%4,%5,%6,%7}, {%8,%9}, {%0,%1,%2,%3};" \
        : "+f"((d)[0]), "+f"((d)[1]), "+f"((d)[2]), "+f"((d)[3]) \
        : "r"((a)[0]), "r"((a)[1]), "r"((a)[2]), "r"((a)[3]), "r"(b0), "r"(b1))

__device__ __forceinline__ uint32_t swz(uint32_t off) {   // SW128 xor swizzle
    return off ^ ((off >> 3) & 0x70);
}

// ---------------- fp16 conversion ----------------
__global__ __launch_bounds__(256) void conv_h(const float* __restrict__ in,
                                              ushort_t* __restrict__ hi, int n4) {
    int i = blockIdx.x * 256 + threadIdx.x;
    if (i >= n4) return;
    float4 v = reinterpret_cast<const float4*>(in)[i];
    ushort4 h;
    h.x = __half_as_ushort(__float2half(v.x));
    h.y = __half_as_ushort(__float2half(v.y));
    h.z = __half_as_ushort(__float2half(v.z));
    h.w = __half_as_ushort(__float2half(v.w));
    reinterpret_cast<ushort4*>(hi)[i] = h;
}

__device__ __forceinline__ float dt_transform(float v, float b) {
    v += b;
    v = fminf(fmaxf(v, -10.0f), 5.0f);
    v = log1pf(expf(v));
    return fminf(fmaxf(v, 1e-4f), 0.1f);
}

// ---------------- HMMA fp16 GEMM: R8 geometry + k-step fragment pipelining --------
// C[m,n] = sum_k A[m,k]*W[n,k]; tile 128x128, BK=64, 8 warps (4x2), 32x64 warp tiles.
// 3 stages x 32KB = 96KB/CTA, 2 CTA/SM, one __syncthreads per K-chunk.
// Fragments for k-step ks+1 are loaded BEFORE the MMAs of k-step ks (double-buffered).
#define TILE_B   16384
#define STAGE_B  32768
#define SM_TOTAL (3 * STAGE_B)   // 98304

__device__ __forceinline__ void stage_load(
    const ushort_t* __restrict__ Ah, const ushort_t* __restrict__ Wh,
    uint32_t sbase, int m0, int n0, int kc, int K, int tid) {
#pragma unroll
    for (int tile = 0; tile < 2; tile++) {
        const ushort_t* g = (tile == 0) ? Ah : Wh;
        int row0 = (tile == 0) ? m0 : n0;
#pragma unroll
        for (int j = 0; j < 4; j++) {
            int idx = tid + j * 256;           // 0..1023
            int row = idx >> 3, seg = idx & 7;
            const ushort_t* src = g + (size_t)(row0 + row) * K + kc + seg * 8;
            uint32_t dst = sbase + tile * TILE_B + swz((uint32_t)(row * 128 + seg * 16));
            CP_ASYNC16(dst, src);
        }
    }
}

__device__ __forceinline__ void ldsm_frags(uint32_t aA, uint32_t aW,
                                           int arow, int akb, int brow, int bkb,
                                           int kb, uint32_t ah[2][4], uint32_t bh[4][4]) {
#pragma unroll
    for (int mi = 0; mi < 2; mi++) {
        uint32_t off = swz((uint32_t)((arow + mi * 16) * 128 + akb + kb));
        LDSM4(ah[mi], aA + off);
    }
#pragma unroll
    for (int ni = 0; ni < 4; ni++) {
        uint32_t off = swz((uint32_t)((brow + ni * 16) * 128 + bkb + kb));
        LDSM4(bh[ni], aW + off);
    }
}

__device__ __forceinline__ void stage_compute(uint32_t sbase, int wm, int wn,
                                              int lane, float acc[2][8][4]) {
    const uint32_t aA = sbase;
    const uint32_t aW = sbase + TILE_B;
    const int arow = wm + (lane & 15);
    const int akb  = (lane >> 4) * 16;
    const int brow = wn + ((lane >> 4) << 3) + (lane & 7);
    const int bkb  = ((lane >> 3) & 1) * 16;

    uint32_t ah[2][2][4], bh[2][4][4];
    ldsm_frags(aA, aW, arow, akb, brow, bkb, 0, ah[0], bh[0]);

#pragma unroll
    for (int ks = 0; ks < 4; ks++) {
        const int cur = ks & 1;
        if (ks < 3)
            ldsm_frags(aA, aW, arow, akb, brow, bkb, (ks + 1) * 32,
                       ah[cur ^ 1], bh[cur ^ 1]);
#pragma unroll
        for (int mi = 0; mi < 2; mi++) {
#pragma unroll
            for (int ni = 0; ni < 4; ni++) {
                MMA_F16(acc[mi][2 * ni + 0], ah[cur][mi], bh[cur][ni][0], bh[cur][ni][1]);
                MMA_F16(acc[mi][2 * ni + 1], ah[cur][mi], bh[cur][ni][2], bh[cur][ni][3]);
            }
        }
    }
}

// OUT16=true : blocks < n1blk write C1h = fp16(A*W1^T); blocks >= n1blk write
//              C2h = fp16(dt_transform(A*W2^T + bias)).
// OUT16=false: all blocks write Cf (fp32) = A*W1^T.
template <bool OUT16>
__global__ __launch_bounds__(256, 2) void gemm_mma(
    const ushort_t* __restrict__ Ah,
    const ushort_t* __restrict__ W1, const ushort_t* __restrict__ W2,
    const float* __restrict__ bias,
    ushort_t* __restrict__ C1h, ushort_t* __restrict__ C2h, float* __restrict__ Cf,
    int n1blk, int N, int K) {
    extern __shared__ __align__(1024) char smem[];
    const uint32_t sb = smem_u32(smem);
    const int tid = threadIdx.x, lane = tid & 31, w = tid >> 5;
    const int m0 = blockIdx.y * 128;
    const bool second = ((int)blockIdx.x >= n1blk);
    const int n0 = (second ? (int)blockIdx.x - n1blk : (int)blockIdx.x) * 128;
    const ushort_t* Wh = second ? W2 : W1;
    const int wm = (w & 3) * 32, wn = (w >> 2) * 64;
    const int NC = K >> 6;

    float acc[2][8][4];
#pragma unroll
    for (int i = 0; i < 2; i++)
#pragma unroll
        for (int j = 0; j < 8; j++)
#pragma unroll
            for (int q = 0; q < 4; q++) acc[i][j][q] = 0.0f;

    stage_load(Ah, Wh, sb + 0 * STAGE_B, m0, n0, 0, K, tid);  CP_COMMIT();
    stage_load(Ah, Wh, sb + 1 * STAGE_B, m0, n0, 64, K, tid); CP_COMMIT();

    int sc = 0, sl = 2;
    for (int c = 0; c < NC; c++) {
        if (c + 1 < NC) { CP_WAIT1(); } else { CP_WAIT0(); }
        __syncthreads();
        // load buffer sl == buffer consumed at iter c-1; all warps are past it (sync above)
        if (c + 2 < NC) {
            stage_load(Ah, Wh, sb + sl * STAGE_B, m0, n0, (c + 2) * 64, K, tid);
            CP_COMMIT();
            sl = (sl == 2) ? 0 : sl + 1;
        }
        stage_compute(sb + sc * STAGE_B, wm, wn, lane, acc);
        sc = (sc == 2) ? 0 : sc + 1;
    }

    // epilogue
    const int gm = m0 + wm, gn = n0 + wn;
    const int r = lane >> 2, cp = (lane & 3) * 2;
#pragma unroll
    for (int mi = 0; mi < 2; mi++) {
#pragma unroll
        for (int nj = 0; nj < 8; nj++) {
            int row = gm + mi * 16 + r;
            int col = gn + nj * 8 + cp;
            float v0 = acc[mi][nj][0], v1 = acc[mi][nj][1];
            float v2 = acc[mi][nj][2], v3 = acc[mi][nj][3];
            if (OUT16) {
                if (second) {
                    float2 bb = *reinterpret_cast<const float2*>(&bias[col]);
                    v0 = dt_transform(v0, bb.x);
                    v1 = dt_transform(v1, bb.y);
                    v2 = dt_transform(v2, bb.x);
                    v3 = dt_transform(v3, bb.y);
                }
                ushort_t* C = second ? C2h : C1h;
                __half2 h01 = __halves2half2(__float2half(v0), __float2half(v1));
                __half2 h23 = __halves2half2(__float2half(v2), __float2half(v3));
                *reinterpret_cast<__half2*>(&C[(size_t)row * N + col]) = h01;
                *reinterpret_cast<__half2*>(&C[(size_t)(row + 8) * N + col]) = h23;
            } else {
                *reinterpret_cast<float2*>(&Cf[(size_t)row * N + col]) = make_float2(v0, v1);
                *reinterpret_cast<float2*>(&Cf[(size_t)(row + 8) * N + col]) = make_float2(v2, v3);
            }
        }
    }
}

// ---------------- B/C projection + row normalization ----------------
__global__ __launch_bounds__(128) void bc_kernel(const float* __restrict__ X,
                                                 const float* __restrict__ WB,
                                                 const float* __restrict__ WC) {
    int warp = threadIdx.x >> 5;
    int lane = threadIdx.x & 31;
    int m = blockIdx.x * 4 + warp;
    const float* Wr = (lane < 16) ? (WB + (size_t)lane * CDMODEL)
                                  : (WC + (size_t)(lane - 16) * CDMODEL);
    const float* Xr = X + (size_t)m * CDMODEL;

    float4 av = make_float4(0.f, 0.f, 0.f, 0.f);
    for (int k = 0; k < CDMODEL; k += 4) {
        float4 xv = *reinterpret_cast<const float4*>(&Xr[k]);
        float4 wv = *reinterpret_cast<const float4*>(&Wr[k]);
        av.x = fmaf(xv.x, wv.x, av.x);
        av.y = fmaf(xv.y, wv.y, av.y);
        av.z = fmaf(xv.z, wv.z, av.z);
        av.w = fmaf(xv.w, wv.w, av.w);
    }
    float acc = (av.x + av.y) + (av.z + av.w);

    float ss = acc * acc;
#pragma unroll
    for (int off = 8; off >= 1; off >>= 1)
        ss += __shfl_xor_sync(0xffffffffu, ss, off);
    float scale = 1.0f / fmaxf(sqrtf(ss), 1.0f);
    float v = acc * scale;
    if (lane < 16) g_Bn[(size_t)m * 16 + lane] = v;
    else           g_Cn[(size_t)m * 16 + (lane - 16)] = v;
}

__device__ __forceinline__ void load16(const float* p, float* v) {
    const float4* q = reinterpret_cast<const float4*>(p);
    float4 a = q[0], b = q[1], c = q[2], d = q[3];
    v[0] = a.x; v[1] = a.y; v[2] = a.z; v[3] = a.w;
    v[4] = b.x; v[5] = b.y; v[6] = b.z; v[7] = b.w;
    v[8] = c.x; v[9] = c.y; v[10] = c.z; v[11] = c.w;
    v[12] = d.x; v[13] = d.y; v[14] = d.z; v[15] = d.w;
}

__device__ __forceinline__ bool load_A(const float* __restrict__ A_log, int d, float* Av) {
    int head = d / CHEADDIM;
    bool fast = true;
#pragma unroll
    for (int n = 0; n < 16; n++) {
        Av[n] = expf(A_log[head * 16 + n]);
        if (fabsf(Av[n] - (float)(n + 1)) > 1e-3f * (float)(n + 1)) fast = false;
    }
    return fast;
}

__device__ __forceinline__ float ldh(const ushort_t* p) {
    return __half2float(__ushort_as_half(*p));
}

// ---------------- scan pass 1: 2 channels/thread (d and d+1024) ----------------
__global__ __launch_bounds__(256) void scan_pass1(const float* __restrict__ A_log) {
    int d0 = blockIdx.x * 256 + threadIdx.x;   // 0..1023
    int d1 = d0 + CHALF;
    int c = blockIdx.y;
    int b = blockIdx.z;

    float Av0[16], Av1[16];
    bool fastA = load_A(A_log, d0, Av0) && load_A(A_log, d1, Av1);

    float h0[16], h1[16];
#pragma unroll
    for (int n = 0; n < 16; n++) { h0[n] = 0.0f; h1[n] = 0.0f; }
    float S0 = 0.0f, S1 = 0.0f;

    int row0 = b * CSEQ + c * CLCHUNK;
    for (int t = 0; t < CLCHUNK; t++) {
        size_t ro = (size_t)(row0 + t) * CDMAMBA + d0;
        float dt0 = ldh(&g_dt16[ro]),         x0 = ldh(&g_x16[ro]);
        float dt1 = ldh(&g_dt16[ro + CHALF]), x1 = ldh(&g_x16[ro + CHALF]);
        float Bv[16];
        load16(g_Bn + (size_t)(row0 + t) * 16, Bv);
        S0 += dt0; S1 += dt1;
        float dtx0 = dt0 * x0, dtx1 = dt1 * x1;
        if (fastA) {
            float r0 = __expf(-dt0), p0 = 1.0f;
            float r1 = __expf(-dt1), p1 = 1.0f;
#pragma unroll
            for (int n = 0; n < 16; n++) {
                p0 *= r0; h0[n] = fmaf(p0, h0[n], dtx0 * Bv[n]);
                p1 *= r1; h1[n] = fmaf(p1, h1[n], dtx1 * Bv[n]);
            }
        } else {
#pragma unroll
            for (int n = 0; n < 16; n++) {
                h0[n] = fmaf(__expf(-dt0 * Av0[n]), h0[n], dtx0 * Bv[n]);
                h1[n] = fmaf(__expf(-dt1 * Av1[n]), h1[n], dtx1 * Bv[n]);
            }
        }
    }
    size_t base = ((size_t)(b * CNCHUNK + c) * 16) * CDMAMBA + d0;
#pragma unroll
    for (int n = 0; n < 16; n++) {
        g_hloc[base + (size_t)n * CDMAMBA] = h0[n];
        g_hloc[base + (size_t)n * CDMAMBA + CHALF] = h1[n];
    }
    g_S[(size_t)(b * CNCHUNK + c) * CDMAMBA + d0] = S0;
    g_S[(size_t)(b * CNCHUNK + c) * CDMAMBA + d1] = S1;
}

// ---------------- scan pass 2 ----------------
__global__ __launch_bounds__(256) void scan_pass2(const float* __restrict__ A_log) {
    int idx = blockIdx.x * 256 + threadIdx.x;
    int b = idx / CDMAMBA;
    int d = idx % CDMAMBA;

    float Av[16];
    bool fastA = load_A(A_log, d, Av);

    float h[16];
#pragma unroll
    for (int n = 0; n < 16; n++) h[n] = 0.0f;

    for (int c = 0; c < CNCHUNK; c++) {
        size_t base = ((size_t)(b * CNCHUNK + c) * 16) * CDMAMBA + d;
#pragma unroll
        for (int n = 0; n < 16; n++) g_hinit[base + (size_t)n * CDMAMBA] = h[n];
        float S = g_S[(size_t)(b * CNCHUNK + c) * CDMAMBA + d];
        if (fastA) {
            float R = __expf(-S), p = 1.0f;
#pragma unroll
            for (int n = 0; n < 16; n++) {
                p *= R;
                h[n] = fmaf(p, h[n], g_hloc[base + (size_t)n * CDMAMBA]);
            }
        } else {
#pragma unroll
            for (int n = 0; n < 16; n++) {
                float P = __expf(-S * Av[n]);
                h[n] = fmaf(P, h[n], g_hloc[base + (size_t)n * CDMAMBA]);
            }
        }
    }
}

// ---------------- scan pass 3: 2 channels/thread, emit y as fp16 ----------------
__global__ __launch_bounds__(256) void scan_pass3(const float* __restrict__ A_log,
                                                  const float* __restrict__ Dvec) {
    int d0 = blockIdx.x * 256 + threadIdx.x;   // 0..1023
    int d1 = d0 + CHALF;
    int c = blockIdx.y;
    int b = blockIdx.z;

    float Av0[16], Av1[16];
    bool fastA = load_A(A_log, d0, Av0) && load_A(A_log, d1, Av1);
    float Dd0 = Dvec[d0], Dd1 = Dvec[d1];

    float h0[16], h1[16];
    size_t base = ((size_t)(b * CNCHUNK + c) * 16) * CDMAMBA + d0;
#pragma unroll
    for (int n = 0; n < 16; n++) {
        h0[n] = g_hinit[base + (size_t)n * CDMAMBA];
        h1[n] = g_hinit[base + (size_t)n * CDMAMBA + CHALF];
    }

    int row0 = b * CSEQ + c * CLCHUNK;
    for (int t = 0; t < CLCHUNK; t++) {
        size_t ro = (size_t)(row0 + t) * CDMAMBA + d0;
        float dt0 = ldh(&g_dt16[ro]),         x0 = ldh(&g_x16[ro]);
        float dt1 = ldh(&g_dt16[ro + CHALF]), x1 = ldh(&g_x16[ro + CHALF]);
        float Bv[16], Cv[16];
        load16(g_Bn + (size_t)(row0 + t) * 16, Bv);
        load16(g_Cn + (size_t)(row0 + t) * 16, Cv);
        float dtx0 = dt0 * x0, dtx1 = dt1 * x1;
        float y0 = 0.0f, y1 = 0.0f;
        if (fastA) {
            float r0 = __expf(-dt0), p0 = 1.0f;
            float r1 = __expf(-dt1), p1 = 1.0f;
#pragma unroll
            for (int n = 0; n < 16; n++) {
                p0 *= r0; h0[n] = fmaf(p0, h0[n], dtx0 * Bv[n]); y0 = fmaf(h0[n], Cv[n], y0);
                p1 *= r1; h1[n] = fmaf(p1, h1[n], dtx1 * Bv[n]); y1 = fmaf(h1[n], Cv[n], y1);
            }
        } else {
#pragma unroll
            for (int n = 0; n < 16; n++) {
                h0[n] = fmaf(__expf(-dt0 * Av0[n]), h0[n], dtx0 * Bv[n]); y0 = fmaf(h0[n], Cv[n], y0);
                h1[n] = fmaf(__expf(-dt1 * Av1[n]), h1[n], dtx1 * Bv[n]); y1 = fmaf(h1[n], Cv[n], y1);
            }
        }
        g_y_h[ro]         = __half_as_ushort(__float2half(fmaf(x0, Dd0, y0)));
        g_y_h[ro + CHALF] = __half_as_ushort(__float2half(fmaf(x1, Dd1, y1)));
    }
}

// ---------------- launch ----------------
extern "C" void kernel_launch(void* const* d_in, const int* in_sizes, int n_in,
                              void* d_out, int out_size) {
    (void)in_sizes; (void)n_in; (void)out_size;
    const float* x_norm     = (const float*)d_in[0];
    const float* x_proj_w   = (const float*)d_in[1];
    const float* dt_proj_w  = (const float*)d_in[2];
    const float* dt_proj_b  = (const float*)d_in[3];
    const float* B_proj_w   = (const float*)d_in[4];
    const float* C_proj_w   = (const float*)d_in[5];
    const float* A_log      = (const float*)d_in[6];
    const float* Dvec       = (const float*)d_in[7];
    const float* out_proj_w = (const float*)d_in[8];
    float* out = (float*)d_out;

    void *p_xnh, *p_w1h, *p_w2h, *p_w3h, *p_yh, *p_x16, *p_dt16;
    cudaGetSymbolAddress(&p_xnh, g_xn_h);
    cudaGetSymbolAddress(&p_w1h, g_w1_h);
    cudaGetSymbolAddress(&p_w2h, g_w2_h);
    cudaGetSymbolAddress(&p_w3h, g_w3_h);
    cudaGetSymbolAddress(&p_yh, g_y_h);
    cudaGetSymbolAddress(&p_x16, g_x16);
    cudaGetSymbolAddress(&p_dt16, g_dt16);

    cudaFuncSetAttribute(gemm_mma<true>, cudaFuncAttributeMaxDynamicSharedMemorySize, SM_TOTAL);
    cudaFuncSetAttribute(gemm_mma<false>, cudaFuncAttributeMaxDynamicSharedMemorySize, SM_TOTAL);

    // fp16 conversions needed by the fused GEMM (launches 0-2)
    {
        int n4 = (CMROWS * CDMODEL) / 4;
        conv_h<<<n4 / 256, 256>>>(x_norm, (ushort_t*)p_xnh, n4);
        n4 = (CDMAMBA * CDMODEL) / 4;
        conv_h<<<n4 / 256, 256>>>(x_proj_w, (ushort_t*)p_w1h, n4);
        conv_h<<<n4 / 256, 256>>>(dt_proj_w, (ushort_t*)p_w2h, n4);
    }

    // 1+2) fused (launch 3 — lands in the ncu capture slot):
    //      x16 = fp16(x_norm @ W1^T) ; dt16 = fp16(dt_transform(x_norm @ W2^T + b))
    {
        dim3 grid(2 * (CDMAMBA / 128), CMROWS / 128);   // (32, 64)
        gemm_mma<true><<<grid, 256, SM_TOTAL>>>(
            (const ushort_t*)p_xnh,
            (const ushort_t*)p_w1h, (const ushort_t*)p_w2h, dt_proj_b,
            (ushort_t*)p_x16, (ushort_t*)p_dt16, nullptr,
            CDMAMBA / 128, CDMAMBA, CDMODEL);
    }

    // W3 conversion (only needed before GEMM3)
    {
        int n4 = (CDMAMBA * CDMAMBA) / 4;
        conv_h<<<n4 / 256, 256>>>(out_proj_w, (ushort_t*)p_w3h, n4);
    }

    // 3) normalized B, C
    bc_kernel<<<CMROWS / 4, 128>>>(x_norm, B_proj_w, C_proj_w);
    // 4-6) chunked selective scan (2 channels per thread in pass1/pass3)
    dim3 scan_grid(CHALF / 256, CNCHUNK, CBATCH);   // (4, 32, 4)
    scan_pass1<<<scan_grid, 256>>>(A_log);
    scan_pass2<<<(CBATCH * CDMAMBA) / 256, 256>>>(A_log);
    scan_pass3<<<scan_grid, 256>>>(A_log, Dvec);
    // 7) out = y @ out_proj_w^T  (fp32 output)
    {
        dim3 grid(CDMAMBA / 128, CMROWS / 128);   // (16, 64)
        gemm_mma<false><<<grid, 256, SM_TOTAL>>>(
            (const ushort_t*)p_yh,
            (const ushort_t*)p_w3h, (const ushort_t*)p_w3h, nullptr,
            nullptr, nullptr, out,
            CDMAMBA / 128, CDMAMBA, CDMAMBA);
    }
}

// round 11
// speedup vs baseline: 1.4109x; 1.3698x over previous
#include <cuda_runtime.h>
#include <cuda_fp16.h>
#include <math.h>
#include <stdint.h>

#define CBATCH   4
#define CSEQ     2048
#define CDMODEL  1024
#define CDMAMBA  2048
#define CDSTATE  16
#define CNHEADS  32
#define CMROWS   (CBATCH * CSEQ)          // 8192
#define CNCHUNK  32
#define CLCHUNK  (CSEQ / CNCHUNK)         // 64
#define CHEADDIM (CDMAMBA / CNHEADS)      // 64
#define CHALF    (CDMAMBA / 2)            // 1024

typedef unsigned short ushort_t;

// ---------------- scratch (static device arrays; no runtime allocation) ----------------
__device__ float g_Bn  [CMROWS * CDSTATE];
__device__ float g_Cn  [CMROWS * CDSTATE];
__device__ float g_hloc [CBATCH * CNCHUNK * CDSTATE * CDMAMBA];
__device__ float g_hinit[CBATCH * CNCHUNK * CDSTATE * CDMAMBA];
__device__ float g_S    [CBATCH * CNCHUNK * CDMAMBA];

// fp16 operands / intermediates
__device__ ushort_t g_xn_h[CMROWS * CDMODEL];
__device__ ushort_t g_w1_h[CDMAMBA * CDMODEL];
__device__ ushort_t g_w2_h[CDMAMBA * CDMODEL];
__device__ ushort_t g_w3_h[CDMAMBA * CDMAMBA];
__device__ ushort_t g_x16 [CMROWS * CDMAMBA];   // x_ssm fp16
__device__ ushort_t g_dt16[CMROWS * CDMAMBA];   // dt fp16
__device__ ushort_t g_y_h [CMROWS * CDMAMBA];   // y fp16

// ---------------- PTX helpers (baseline sm_80-level features only) ----------------
__device__ __forceinline__ uint32_t smem_u32(const void* p) {
    uint32_t a;
    asm("{ .reg .u64 t; cvta.to.shared.u64 t, %1; cvt.u32.u64 %0, t; }" : "=r"(a) : "l"(p));
    return a;
}

#define CP_ASYNC16(dst, src) \
    asm volatile("cp.async.cg.shared.global [%0], [%1], 16;" :: "r"(dst), "l"(src))
#define CP_COMMIT() asm volatile("cp.async.commit_group;" ::: "memory")
#define CP_WAIT0() asm volatile("cp.async.wait_group 0;" ::: "memory")
#define CP_WAIT1() asm volatile("cp.async.wait_group 1;" ::: "memory")

#define LDSM4(r, addr) \
    asm volatile("ldmatrix.sync.aligned.m8n8.x4.shared.b16 {%0,%1,%2,%3}, [%4];" \
        : "=r"((r)[0]), "=r"((r)[1]), "=r"((r)[2]), "=r"((r)[3]) : "r"(addr))

#define MMA_F16(d, a, b0, b1) \
    asm volatile("mma.sync.aligned.m16n8k16.row.col.f32.f16.f16.f32 " \
        "{%0,%1,%2,%3}, {%4,%5,%6,%7}, {%8,%9}, {%0,%1,%2,%3};" \
        : "+f"((d)[0]), "+f"((d)[1]), "+f"((d)[2]), "+f"((d)[3]) \
        : "r"((a)[0]), "r"((a)[1]), "r"((a)[2]), "r"((a)[3]), "r"(b0), "r"(b1))

__device__ __forceinline__ uint32_t swz(uint32_t off) {   // SW128 xor swizzle
    return off ^ ((off >> 3) & 0x70);
}

// ---------------- fp16 conversion ----------------
__global__ __launch_bounds__(256) void conv_h(const float* __restrict__ in,
                                              ushort_t* __restrict__ hi, int n4) {
    int i = blockIdx.x * 256 + threadIdx.x;
    if (i >= n4) return;
    float4 v = reinterpret_cast<const float4*>(in)[i];
    ushort4 h;
    h.x = __half_as_ushort(__float2half(v.x));
    h.y = __half_as_ushort(__float2half(v.y));
    h.z = __half_as_ushort(__float2half(v.z));
    h.w = __half_as_ushort(__float2half(v.w));
    reinterpret_cast<ushort4*>(hi)[i] = h;
}

__device__ __forceinline__ float dt_transform(float v, float b) {
    v += b;
    v = fminf(fmaxf(v, -10.0f), 5.0f);
    v = log1pf(expf(v));
    return fminf(fmaxf(v, 1e-4f), 0.1f);
}

// ---------------- HMMA fp16 GEMM: R8 geometry + k-step fragment pipelining --------
#define TILE_B   16384
#define STAGE_B  32768
#define SM_TOTAL (3 * STAGE_B)   // 98304

__device__ __forceinline__ void stage_load(
    const ushort_t* __restrict__ Ah, const ushort_t* __restrict__ Wh,
    uint32_t sbase, int m0, int n0, int kc, int K, int tid) {
#pragma unroll
    for (int tile = 0; tile < 2; tile++) {
        const ushort_t* g = (tile == 0) ? Ah : Wh;
        int row0 = (tile == 0) ? m0 : n0;
#pragma unroll
        for (int j = 0; j < 4; j++) {
            int idx = tid + j * 256;           // 0..1023
            int row = idx >> 3, seg = idx & 7;
            const ushort_t* src = g + (size_t)(row0 + row) * K + kc + seg * 8;
            uint32_t dst = sbase + tile * TILE_B + swz((uint32_t)(row * 128 + seg * 16));
            CP_ASYNC16(dst, src);
        }
    }
}

__device__ __forceinline__ void ldsm_frags(uint32_t aA, uint32_t aW,
                                           int arow, int akb, int brow, int bkb,
                                           int kb, uint32_t ah[2][4], uint32_t bh[4][4]) {
#pragma unroll
    for (int mi = 0; mi < 2; mi++) {
        uint32_t off = swz((uint32_t)((arow + mi * 16) * 128 + akb + kb));
        LDSM4(ah[mi], aA + off);
    }
#pragma unroll
    for (int ni = 0; ni < 4; ni++) {
        uint32_t off = swz((uint32_t)((brow + ni * 16) * 128 + bkb + kb));
        LDSM4(bh[ni], aW + off);
    }
}

__device__ __forceinline__ void stage_compute(uint32_t sbase, int wm, int wn,
                                              int lane, float acc[2][8][4]) {
    const uint32_t aA = sbase;
    const uint32_t aW = sbase + TILE_B;
    const int arow = wm + (lane & 15);
    const int akb  = (lane >> 4) * 16;
    const int brow = wn + ((lane >> 4) << 3) + (lane & 7);
    const int bkb  = ((lane >> 3) & 1) * 16;

    uint32_t ah[2][2][4], bh[2][4][4];
    ldsm_frags(aA, aW, arow, akb, brow, bkb, 0, ah[0], bh[0]);

#pragma unroll
    for (int ks = 0; ks < 4; ks++) {
        const int cur = ks & 1;
        if (ks < 3)
            ldsm_frags(aA, aW, arow, akb, brow, bkb, (ks + 1) * 32,
                       ah[cur ^ 1], bh[cur ^ 1]);
#pragma unroll
        for (int mi = 0; mi < 2; mi++) {
#pragma unroll
            for (int ni = 0; ni < 4; ni++) {
                MMA_F16(acc[mi][2 * ni + 0], ah[cur][mi], bh[cur][ni][0], bh[cur][ni][1]);
                MMA_F16(acc[mi][2 * ni + 1], ah[cur][mi], bh[cur][ni][2], bh[cur][ni][3]);
            }
        }
    }
}

template <bool OUT16>
__global__ __launch_bounds__(256, 2) void gemm_mma(
    const ushort_t* __restrict__ Ah,
    const ushort_t* __restrict__ W1, const ushort_t* __restrict__ W2,
    const float* __restrict__ bias,
    ushort_t* __restrict__ C1h, ushort_t* __restrict__ C2h, float* __restrict__ Cf,
    int n1blk, int N, int K) {
    extern __shared__ __align__(1024) char smem[];
    const uint32_t sb = smem_u32(smem);
    const int tid = threadIdx.x, lane = tid & 31, w = tid >> 5;
    const int m0 = blockIdx.y * 128;
    const bool second = ((int)blockIdx.x >= n1blk);
    const int n0 = (second ? (int)blockIdx.x - n1blk : (int)blockIdx.x) * 128;
    const ushort_t* Wh = second ? W2 : W1;
    const int wm = (w & 3) * 32, wn = (w >> 2) * 64;
    const int NC = K >> 6;

    float acc[2][8][4];
#pragma unroll
    for (int i = 0; i < 2; i++)
#pragma unroll
        for (int j = 0; j < 8; j++)
#pragma unroll
            for (int q = 0; q < 4; q++) acc[i][j][q] = 0.0f;

    stage_load(Ah, Wh, sb + 0 * STAGE_B, m0, n0, 0, K, tid);  CP_COMMIT();
    stage_load(Ah, Wh, sb + 1 * STAGE_B, m0, n0, 64, K, tid); CP_COMMIT();

    int sc = 0, sl = 2;
    for (int c = 0; c < NC; c++) {
        if (c + 1 < NC) { CP_WAIT1(); } else { CP_WAIT0(); }
        __syncthreads();
        if (c + 2 < NC) {
            stage_load(Ah, Wh, sb + sl * STAGE_B, m0, n0, (c + 2) * 64, K, tid);
            CP_COMMIT();
            sl = (sl == 2) ? 0 : sl + 1;
        }
        stage_compute(sb + sc * STAGE_B, wm, wn, lane, acc);
        sc = (sc == 2) ? 0 : sc + 1;
    }

    // epilogue
    const int gm = m0 + wm, gn = n0 + wn;
    const int r = lane >> 2, cp = (lane & 3) * 2;
#pragma unroll
    for (int mi = 0; mi < 2; mi++) {
#pragma unroll
        for (int nj = 0; nj < 8; nj++) {
            int row = gm + mi * 16 + r;
            int col = gn + nj * 8 + cp;
            float v0 = acc[mi][nj][0], v1 = acc[mi][nj][1];
            float v2 = acc[mi][nj][2], v3 = acc[mi][nj][3];
            if (OUT16) {
                if (second) {
                    float2 bb = *reinterpret_cast<const float2*>(&bias[col]);
                    v0 = dt_transform(v0, bb.x);
                    v1 = dt_transform(v1, bb.y);
                    v2 = dt_transform(v2, bb.x);
                    v3 = dt_transform(v3, bb.y);
                }
                ushort_t* C = second ? C2h : C1h;
                __half2 h01 = __halves2half2(__float2half(v0), __float2half(v1));
                __half2 h23 = __halves2half2(__float2half(v2), __float2half(v3));
                *reinterpret_cast<__half2*>(&C[(size_t)row * N + col]) = h01;
                *reinterpret_cast<__half2*>(&C[(size_t)(row + 8) * N + col]) = h23;
            } else {
                *reinterpret_cast<float2*>(&Cf[(size_t)row * N + col]) = make_float2(v0, v1);
                *reinterpret_cast<float2*>(&Cf[(size_t)(row + 8) * N + col]) = make_float2(v2, v3);
            }
        }
    }
}

// ---------------- B/C projection + normalization (smem-tiled, coalesced) ----------------
// Block: 256 threads, 64 M-rows, 32 outputs (B:0-15, C:16-31). K-tiles of 64.
// Warp ty covers rows [ty*8, ty*8+8), lane tx = output index n.
__global__ __launch_bounds__(256) void bc_kernel(const float* __restrict__ X,
                                                 const float* __restrict__ WB,
                                                 const float* __restrict__ WC) {
    __shared__ float Xs[64][65];
    __shared__ float Ws[32][65];
    const int tid = threadIdx.x;
    const int tx = tid & 31;        // n (0-15 -> B, 16-31 -> C)
    const int ty = tid >> 5;        // warp 0..7
    const int m0 = blockIdx.x * 64;

    float acc[8];
#pragma unroll
    for (int i = 0; i < 8; i++) acc[i] = 0.0f;

    for (int kt = 0; kt < CDMODEL; kt += 64) {
#pragma unroll
        for (int j = 0; j < 4; j++) {
            int q = tid + j * 256;            // 0..1023 float4 quanta
            int row = q >> 4;
            int c4 = (q & 15) * 4;
            float4 v = *reinterpret_cast<const float4*>(&X[(size_t)(m0 + row) * CDMODEL + kt + c4]);
            Xs[row][c4 + 0] = v.x; Xs[row][c4 + 1] = v.y;
            Xs[row][c4 + 2] = v.z; Xs[row][c4 + 3] = v.w;
        }
#pragma unroll
        for (int j = 0; j < 2; j++) {
            int q = tid + j * 256;            // 0..511
            int row = q >> 4;
            int c4 = (q & 15) * 4;
            const float* Wsrc = (row < 16) ? &WB[(size_t)row * CDMODEL]
                                           : &WC[(size_t)(row - 16) * CDMODEL];
            float4 v = *reinterpret_cast<const float4*>(&Wsrc[kt + c4]);
            Ws[row][c4 + 0] = v.x; Ws[row][c4 + 1] = v.y;
            Ws[row][c4 + 2] = v.z; Ws[row][c4 + 3] = v.w;
        }
        __syncthreads();
#pragma unroll 8
        for (int k = 0; k < 64; k++) {
            float wv = Ws[tx][k];             // conflict-free: bank = (tx*65+k)%32 distinct
#pragma unroll
            for (int i = 0; i < 8; i++)
                acc[i] = fmaf(Xs[ty * 8 + i][k], wv, acc[i]);  // broadcast per warp
        }
        __syncthreads();
    }

#pragma unroll
    for (int i = 0; i < 8; i++) {
        float v = acc[i];
        float ss = v * v;
#pragma unroll
        for (int off = 8; off >= 1; off >>= 1)
            ss += __shfl_xor_sync(0xffffffffu, ss, off);   // stays within 16-lane halves
        float sc = 1.0f / fmaxf(sqrtf(ss), 1.0f);
        v *= sc;
        int m = m0 + ty * 8 + i;
        if (tx < 16) g_Bn[(size_t)m * 16 + tx] = v;
        else         g_Cn[(size_t)m * 16 + (tx - 16)] = v;
    }
}

__device__ __forceinline__ void load16(const float* p, float* v) {
    const float4* q = reinterpret_cast<const float4*>(p);
    float4 a = q[0], b = q[1], c = q[2], d = q[3];
    v[0] = a.x; v[1] = a.y; v[2] = a.z; v[3] = a.w;
    v[4] = b.x; v[5] = b.y; v[6] = b.z; v[7] = b.w;
    v[8] = c.x; v[9] = c.y; v[10] = c.z; v[11] = c.w;
    v[12] = d.x; v[13] = d.y; v[14] = d.z; v[15] = d.w;
}

__device__ __forceinline__ bool load_A(const float* __restrict__ A_log, int d, float* Av) {
    int head = d / CHEADDIM;
    bool fast = true;
#pragma unroll
    for (int n = 0; n < 16; n++) {
        Av[n] = expf(A_log[head * 16 + n]);
        if (fabsf(Av[n] - (float)(n + 1)) > 1e-3f * (float)(n + 1)) fast = false;
    }
    return fast;
}

__device__ __forceinline__ float ldh(const ushort_t* p) {
    return __half2float(__ushort_as_half(*p));
}

// ---------------- scan pass 1: 2 channels/thread (d and d+1024) ----------------
__global__ __launch_bounds__(256) void scan_pass1(const float* __restrict__ A_log) {
    int d0 = blockIdx.x * 256 + threadIdx.x;   // 0..1023
    int d1 = d0 + CHALF;
    int c = blockIdx.y;
    int b = blockIdx.z;

    float Av0[16], Av1[16];
    bool fastA = load_A(A_log, d0, Av0) && load_A(A_log, d1, Av1);

    float h0[16], h1[16];
#pragma unroll
    for (int n = 0; n < 16; n++) { h0[n] = 0.0f; h1[n] = 0.0f; }
    float S0 = 0.0f, S1 = 0.0f;

    int row0 = b * CSEQ + c * CLCHUNK;
    for (int t = 0; t < CLCHUNK; t++) {
        size_t ro = (size_t)(row0 + t) * CDMAMBA + d0;
        float dt0 = ldh(&g_dt16[ro]),         x0 = ldh(&g_x16[ro]);
        float dt1 = ldh(&g_dt16[ro + CHALF]), x1 = ldh(&g_x16[ro + CHALF]);
        float Bv[16];
        load16(g_Bn + (size_t)(row0 + t) * 16, Bv);
        S0 += dt0; S1 += dt1;
        float dtx0 = dt0 * x0, dtx1 = dt1 * x1;
        if (fastA) {
            float r0 = __expf(-dt0), p0 = 1.0f;
            float r1 = __expf(-dt1), p1 = 1.0f;
#pragma unroll
            for (int n = 0; n < 16; n++) {
                p0 *= r0; h0[n] = fmaf(p0, h0[n], dtx0 * Bv[n]);
                p1 *= r1; h1[n] = fmaf(p1, h1[n], dtx1 * Bv[n]);
            }
        } else {
#pragma unroll
            for (int n = 0; n < 16; n++) {
                h0[n] = fmaf(__expf(-dt0 * Av0[n]), h0[n], dtx0 * Bv[n]);
                h1[n] = fmaf(__expf(-dt1 * Av1[n]), h1[n], dtx1 * Bv[n]);
            }
        }
    }
    size_t base = ((size_t)(b * CNCHUNK + c) * 16) * CDMAMBA + d0;
#pragma unroll
    for (int n = 0; n < 16; n++) {
        g_hloc[base + (size_t)n * CDMAMBA] = h0[n];
        g_hloc[base + (size_t)n * CDMAMBA + CHALF] = h1[n];
    }
    g_S[(size_t)(b * CNCHUNK + c) * CDMAMBA + d0] = S0;
    g_S[(size_t)(b * CNCHUNK + c) * CDMAMBA + d1] = S1;
}

// ---------------- scan pass 2: one (b, n, d) chain per thread ----------------
__global__ __launch_bounds__(256) void scan_pass2(const float* __restrict__ A_log) {
    int idx = blockIdx.x * 256 + threadIdx.x;   // 0 .. B*16*2048-1
    int d = idx % CDMAMBA;
    int bn = idx / CDMAMBA;
    int n = bn & 15;
    int b = bn >> 4;

    int head = d / CHEADDIM;
    float An = expf(A_log[head * 16 + n]);

    float h = 0.0f;
    for (int c = 0; c < CNCHUNK; c++) {
        size_t sidx = (size_t)(b * CNCHUNK + c) * CDMAMBA + d;
        size_t hidx = ((size_t)(b * CNCHUNK + c) * 16 + n) * CDMAMBA + d;
        g_hinit[hidx] = h;
        float S = g_S[sidx];
        h = fmaf(__expf(-S * An), h, g_hloc[hidx]);
    }
}

// ---------------- scan pass 3: 2 channels/thread, emit y as fp16 ----------------
__global__ __launch_bounds__(256) void scan_pass3(const float* __restrict__ A_log,
                                                  const float* __restrict__ Dvec) {
    int d0 = blockIdx.x * 256 + threadIdx.x;   // 0..1023
    int d1 = d0 + CHALF;
    int c = blockIdx.y;
    int b = blockIdx.z;

    float Av0[16], Av1[16];
    bool fastA = load_A(A_log, d0, Av0) && load_A(A_log, d1, Av1);
    float Dd0 = Dvec[d0], Dd1 = Dvec[d1];

    float h0[16], h1[16];
    size_t base = ((size_t)(b * CNCHUNK + c) * 16) * CDMAMBA + d0;
#pragma unroll
    for (int n = 0; n < 16; n++) {
        h0[n] = g_hinit[base + (size_t)n * CDMAMBA];
        h1[n] = g_hinit[base + (size_t)n * CDMAMBA + CHALF];
    }

    int row0 = b * CSEQ + c * CLCHUNK;
    for (int t = 0; t < CLCHUNK; t++) {
        size_t ro = (size_t)(row0 + t) * CDMAMBA + d0;
        float dt0 = ldh(&g_dt16[ro]),         x0 = ldh(&g_x16[ro]);
        float dt1 = ldh(&g_dt16[ro + CHALF]), x1 = ldh(&g_x16[ro + CHALF]);
        float Bv[16], Cv[16];
        load16(g_Bn + (size_t)(row0 + t) * 16, Bv);
        load16(g_Cn + (size_t)(row0 + t) * 16, Cv);
        float dtx0 = dt0 * x0, dtx1 = dt1 * x1;
        float y0 = 0.0f, y1 = 0.0f;
        if (fastA) {
            float r0 = __expf(-dt0), p0 = 1.0f;
            float r1 = __expf(-dt1), p1 = 1.0f;
#pragma unroll
            for (int n = 0; n < 16; n++) {
                p0 *= r0; h0[n] = fmaf(p0, h0[n], dtx0 * Bv[n]); y0 = fmaf(h0[n], Cv[n], y0);
                p1 *= r1; h1[n] = fmaf(p1, h1[n], dtx1 * Bv[n]); y1 = fmaf(h1[n], Cv[n], y1);
            }
        } else {
#pragma unroll
            for (int n = 0; n < 16; n++) {
                h0[n] = fmaf(__expf(-dt0 * Av0[n]), h0[n], dtx0 * Bv[n]); y0 = fmaf(h0[n], Cv[n], y0);
                h1[n] = fmaf(__expf(-dt1 * Av1[n]), h1[n], dtx1 * Bv[n]); y1 = fmaf(h1[n], Cv[n], y1);
            }
        }
        g_y_h[ro]         = __half_as_ushort(__float2half(fmaf(x0, Dd0, y0)));
        g_y_h[ro + CHALF] = __half_as_ushort(__float2half(fmaf(x1, Dd1, y1)));
    }
}

// ---------------- launch ----------------
extern "C" void kernel_launch(void* const* d_in, const int* in_sizes, int n_in,
                              void* d_out, int out_size) {
    (void)in_sizes; (void)n_in; (void)out_size;
    const float* x_norm     = (const float*)d_in[0];
    const float* x_proj_w   = (const float*)d_in[1];
    const float* dt_proj_w  = (const float*)d_in[2];
    const float* dt_proj_b  = (const float*)d_in[3];
    const float* B_proj_w   = (const float*)d_in[4];
    const float* C_proj_w   = (const float*)d_in[5];
    const float* A_log      = (const float*)d_in[6];
    const float* Dvec       = (const float*)d_in[7];
    const float* out_proj_w = (const float*)d_in[8];
    float* out = (float*)d_out;

    void *p_xnh, *p_w1h, *p_w2h, *p_w3h, *p_yh, *p_x16, *p_dt16;
    cudaGetSymbolAddress(&p_xnh, g_xn_h);
    cudaGetSymbolAddress(&p_w1h, g_w1_h);
    cudaGetSymbolAddress(&p_w2h, g_w2_h);
    cudaGetSymbolAddress(&p_w3h, g_w3_h);
    cudaGetSymbolAddress(&p_yh, g_y_h);
    cudaGetSymbolAddress(&p_x16, g_x16);
    cudaGetSymbolAddress(&p_dt16, g_dt16);

    cudaFuncSetAttribute(gemm_mma<true>, cudaFuncAttributeMaxDynamicSharedMemorySize, SM_TOTAL);
    cudaFuncSetAttribute(gemm_mma<false>, cudaFuncAttributeMaxDynamicSharedMemorySize, SM_TOTAL);

    // fp16 conversions needed by the fused GEMM (launches 0-2)
    {
        int n4 = (CMROWS * CDMODEL) / 4;
        conv_h<<<n4 / 256, 256>>>(x_norm, (ushort_t*)p_xnh, n4);
        n4 = (CDMAMBA * CDMODEL) / 4;
        conv_h<<<n4 / 256, 256>>>(x_proj_w, (ushort_t*)p_w1h, n4);
        conv_h<<<n4 / 256, 256>>>(dt_proj_w, (ushort_t*)p_w2h, n4);
    }

    // normalized B, C (launch 3 — lands in the ncu capture slot)
    bc_kernel<<<CMROWS / 64, 256>>>(x_norm, B_proj_w, C_proj_w);

    // 1+2) fused: x16 = fp16(x_norm @ W1^T) ; dt16 = fp16(dt_transform(x_norm @ W2^T + b))
    {
        dim3 grid(2 * (CDMAMBA / 128), CMROWS / 128);   // (32, 64)
        gemm_mma<true><<<grid, 256, SM_TOTAL>>>(
            (const ushort_t*)p_xnh,
            (const ushort_t*)p_w1h, (const ushort_t*)p_w2h, dt_proj_b,
            (ushort_t*)p_x16, (ushort_t*)p_dt16, nullptr,
            CDMAMBA / 128, CDMAMBA, CDMODEL);
    }

    // W3 conversion (only needed before GEMM3)
    {
        int n4 = (CDMAMBA * CDMAMBA) / 4;
        conv_h<<<n4 / 256, 256>>>(out_proj_w, (ushort_t*)p_w3h, n4);
    }

    // 4-6) chunked selective scan
    dim3 scan_grid(CHALF / 256, CNCHUNK, CBATCH);   // (4, 32, 4)
    scan_pass1<<<scan_grid, 256>>>(A_log);
    scan_pass2<<<(CBATCH * 16 * CDMAMBA) / 256, 256>>>(A_log);   // 512 blocks
    scan_pass3<<<scan_grid, 256>>>(A_log, Dvec);
    // 7) out = y @ out_proj_w^T  (fp32 output)
    {
        dim3 grid(CDMAMBA / 128, CMROWS / 128);   // (16, 64)
        gemm_mma<false><<<grid, 256, SM_TOTAL>>>(
            (const ushort_t*)p_yh,
            (const ushort_t*)p_w3h, (const ushort_t*)p_w3h, nullptr,
            nullptr, nullptr, out,
            CDMAMBA / 128, CDMAMBA, CDMAMBA);
    }
}

// round 12
// speedup vs baseline: 1.4202x; 1.0066x over previous
#include <cuda_runtime.h>
#include <cuda_fp16.h>
#include <math.h>
#include <stdint.h>

#define CBATCH   4
#define CSEQ     2048
#define CDMODEL  1024
#define CDMAMBA  2048
#define CDSTATE  16
#define CNHEADS  32
#define CMROWS   (CBATCH * CSEQ)          // 8192
#define CNCHUNK  32
#define CLCHUNK  (CSEQ / CNCHUNK)         // 64
#define CHEADDIM (CDMAMBA / CNHEADS)      // 64

typedef unsigned short ushort_t;
typedef unsigned long long ull_t;

// ---------------- scratch (static device arrays; no runtime allocation) ----------------
__device__ float g_Bn  [CMROWS * CDSTATE];
__device__ float g_Cn  [CMROWS * CDSTATE];
__device__ float g_hloc [CBATCH * CNCHUNK * CDSTATE * CDMAMBA];
__device__ float g_hinit[CBATCH * CNCHUNK * CDSTATE * CDMAMBA];
__device__ float g_S    [CBATCH * CNCHUNK * CDMAMBA];

// fp16 operands / intermediates
__device__ ushort_t g_xn_h[CMROWS * CDMODEL];
__device__ ushort_t g_w1_h[CDMAMBA * CDMODEL];
__device__ ushort_t g_w2_h[CDMAMBA * CDMODEL];
__device__ ushort_t g_w3_h[CDMAMBA * CDMAMBA];
__device__ ushort_t g_x16 [CMROWS * CDMAMBA];   // x_ssm fp16
__device__ ushort_t g_dt16[CMROWS * CDMAMBA];   // dt fp16
__device__ ushort_t g_y_h [CMROWS * CDMAMBA];   // y fp16

// ---------------- PTX helpers ----------------
__device__ __forceinline__ uint32_t smem_u32(const void* p) {
    uint32_t a;
    asm("{ .reg .u64 t; cvta.to.shared.u64 t, %1; cvt.u32.u64 %0, t; }" : "=r"(a) : "l"(p));
    return a;
}

#define CP_ASYNC16(dst, src) \
    asm volatile("cp.async.cg.shared.global [%0], [%1], 16;" :: "r"(dst), "l"(src))
#define CP_COMMIT() asm volatile("cp.async.commit_group;" ::: "memory")
#define CP_WAIT0() asm volatile("cp.async.wait_group 0;" ::: "memory")
#define CP_WAIT1() asm volatile("cp.async.wait_group 1;" ::: "memory")

#define LDSM4(r, addr) \
    asm volatile("ldmatrix.sync.aligned.m8n8.x4.shared.b16 {%0,%1,%2,%3}, [%4];" \
        : "=r"((r)[0]), "=r"((r)[1]), "=r"((r)[2]), "=r"((r)[3]) : "r"(addr))

#define MMA_F16(d, a, b0, b1) \
    asm volatile("mma.sync.aligned.m16n8k16.row.col.f32.f16.f16.f32 " \
        "{%0,%1,%2,%3}, {%4,%5,%6,%7}, {%8,%9}, {%0,%1,%2,%3};" \
        : "+f"((d)[0]), "+f"((d)[1]), "+f"((d)[2]), "+f"((d)[3]) \
        : "r"((a)[0]), "r"((a)[1]), "r"((a)[2]), "r"((a)[3]), "r"(b0), "r"(b1))

__device__ __forceinline__ uint32_t swz(uint32_t off) {   // SW128 xor swizzle
    return off ^ ((off >> 3) & 0x70);
}

// packed f32x2 (Blackwell FFMA2 path; baseline-PTX legal)
__device__ __forceinline__ ull_t pk2(float lo, float hi) {
    ull_t r; asm("mov.b64 %0, {%1, %2};" : "=l"(r) : "f"(lo), "f"(hi)); return r;
}
__device__ __forceinline__ void upk2(ull_t v, float& lo, float& hi) {
    asm("mov.b64 {%0, %1}, %2;" : "=f"(lo), "=f"(hi) : "l"(v));
}
__device__ __forceinline__ ull_t mul2(ull_t a, ull_t b) {
    ull_t r; asm("mul.rn.f32x2 %0, %1, %2;" : "=l"(r) : "l"(a), "l"(b)); return r;
}
__device__ __forceinline__ ull_t fma2(ull_t a, ull_t b, ull_t c) {  // a*b + c
    ull_t r; asm("fma.rn.f32x2 %0, %1, %2, %3;" : "=l"(r) : "l"(a), "l"(b), "l"(c)); return r;
}

// ---------------- fp16 conversion ----------------
__global__ __launch_bounds__(256) void conv_h(const float* __restrict__ in,
                                              ushort_t* __restrict__ hi, int n4) {
    int i = blockIdx.x * 256 + threadIdx.x;
    if (i >= n4) return;
    float4 v = reinterpret_cast<const float4*>(in)[i];
    ushort4 h;
    h.x = __half_as_ushort(__float2half(v.x));
    h.y = __half_as_ushort(__float2half(v.y));
    h.z = __half_as_ushort(__float2half(v.z));
    h.w = __half_as_ushort(__float2half(v.w));
    reinterpret_cast<ushort4*>(hi)[i] = h;
}

__device__ __forceinline__ float dt_transform(float v, float b) {
    v += b;
    v = fminf(fmaxf(v, -10.0f), 5.0f);
    v = log1pf(expf(v));
    return fminf(fmaxf(v, 1e-4f), 0.1f);
}

// ---------------- HMMA fp16 GEMM (unchanged champion: R8 geometry + frag pipelining) ----
#define TILE_B   16384
#define STAGE_B  32768
#define SM_TOTAL (3 * STAGE_B)   // 98304

__device__ __forceinline__ void stage_load(
    const ushort_t* __restrict__ Ah, const ushort_t* __restrict__ Wh,
    uint32_t sbase, int m0, int n0, int kc, int K, int tid) {
#pragma unroll
    for (int tile = 0; tile < 2; tile++) {
        const ushort_t* g = (tile == 0) ? Ah : Wh;
        int row0 = (tile == 0) ? m0 : n0;
#pragma unroll
        for (int j = 0; j < 4; j++) {
            int idx = tid + j * 256;
            int row = idx >> 3, seg = idx & 7;
            const ushort_t* src = g + (size_t)(row0 + row) * K + kc + seg * 8;
            uint32_t dst = sbase + tile * TILE_B + swz((uint32_t)(row * 128 + seg * 16));
            CP_ASYNC16(dst, src);
        }
    }
}

__device__ __forceinline__ void ldsm_frags(uint32_t aA, uint32_t aW,
                                           int arow, int akb, int brow, int bkb,
                                           int kb, uint32_t ah[2][4], uint32_t bh[4][4]) {
#pragma unroll
    for (int mi = 0; mi < 2; mi++) {
        uint32_t off = swz((uint32_t)((arow + mi * 16) * 128 + akb + kb));
        LDSM4(ah[mi], aA + off);
    }
#pragma unroll
    for (int ni = 0; ni < 4; ni++) {
        uint32_t off = swz((uint32_t)((brow + ni * 16) * 128 + bkb + kb));
        LDSM4(bh[ni], aW + off);
    }
}

__device__ __forceinline__ void stage_compute(uint32_t sbase, int wm, int wn,
                                              int lane, float acc[2][8][4]) {
    const uint32_t aA = sbase;
    const uint32_t aW = sbase + TILE_B;
    const int arow = wm + (lane & 15);
    const int akb  = (lane >> 4) * 16;
    const int brow = wn + ((lane >> 4) << 3) + (lane & 7);
    const int bkb  = ((lane >> 3) & 1) * 16;

    uint32_t ah[2][2][4], bh[2][4][4];
    ldsm_frags(aA, aW, arow, akb, brow, bkb, 0, ah[0], bh[0]);

#pragma unroll
    for (int ks = 0; ks < 4; ks++) {
        const int cur = ks & 1;
        if (ks < 3)
            ldsm_frags(aA, aW, arow, akb, brow, bkb, (ks + 1) * 32,
                       ah[cur ^ 1], bh[cur ^ 1]);
#pragma unroll
        for (int mi = 0; mi < 2; mi++) {
#pragma unroll
            for (int ni = 0; ni < 4; ni++) {
                MMA_F16(acc[mi][2 * ni + 0], ah[cur][mi], bh[cur][ni][0], bh[cur][ni][1]);
                MMA_F16(acc[mi][2 * ni + 1], ah[cur][mi], bh[cur][ni][2], bh[cur][ni][3]);
            }
        }
    }
}

template <bool OUT16>
__global__ __launch_bounds__(256, 2) void gemm_mma(
    const ushort_t* __restrict__ Ah,
    const ushort_t* __restrict__ W1, const ushort_t* __restrict__ W2,
    const float* __restrict__ bias,
    ushort_t* __restrict__ C1h, ushort_t* __restrict__ C2h, float* __restrict__ Cf,
    int n1blk, int N, int K) {
    extern __shared__ __align__(1024) char smem[];
    const uint32_t sb = smem_u32(smem);
    const int tid = threadIdx.x, lane = tid & 31, w = tid >> 5;
    const int m0 = blockIdx.y * 128;
    const bool second = ((int)blockIdx.x >= n1blk);
    const int n0 = (second ? (int)blockIdx.x - n1blk : (int)blockIdx.x) * 128;
    const ushort_t* Wh = second ? W2 : W1;
    const int wm = (w & 3) * 32, wn = (w >> 2) * 64;
    const int NC = K >> 6;

    float acc[2][8][4];
#pragma unroll
    for (int i = 0; i < 2; i++)
#pragma unroll
        for (int j = 0; j < 8; j++)
#pragma unroll
            for (int q = 0; q < 4; q++) acc[i][j][q] = 0.0f;

    stage_load(Ah, Wh, sb + 0 * STAGE_B, m0, n0, 0, K, tid);  CP_COMMIT();
    stage_load(Ah, Wh, sb + 1 * STAGE_B, m0, n0, 64, K, tid); CP_COMMIT();

    int sc = 0, sl = 2;
    for (int c = 0; c < NC; c++) {
        if (c + 1 < NC) { CP_WAIT1(); } else { CP_WAIT0(); }
        __syncthreads();
        if (c + 2 < NC) {
            stage_load(Ah, Wh, sb + sl * STAGE_B, m0, n0, (c + 2) * 64, K, tid);
            CP_COMMIT();
            sl = (sl == 2) ? 0 : sl + 1;
        }
        stage_compute(sb + sc * STAGE_B, wm, wn, lane, acc);
        sc = (sc == 2) ? 0 : sc + 1;
    }

    const int gm = m0 + wm, gn = n0 + wn;
    const int r = lane >> 2, cp = (lane & 3) * 2;
#pragma unroll
    for (int mi = 0; mi < 2; mi++) {
#pragma unroll
        for (int nj = 0; nj < 8; nj++) {
            int row = gm + mi * 16 + r;
            int col = gn + nj * 8 + cp;
            float v0 = acc[mi][nj][0], v1 = acc[mi][nj][1];
            float v2 = acc[mi][nj][2], v3 = acc[mi][nj][3];
            if (OUT16) {
                if (second) {
                    float2 bb = *reinterpret_cast<const float2*>(&bias[col]);
                    v0 = dt_transform(v0, bb.x);
                    v1 = dt_transform(v1, bb.y);
                    v2 = dt_transform(v2, bb.x);
                    v3 = dt_transform(v3, bb.y);
                }
                ushort_t* C = second ? C2h : C1h;
                __half2 h01 = __halves2half2(__float2half(v0), __float2half(v1));
                __half2 h23 = __halves2half2(__float2half(v2), __float2half(v3));
                *reinterpret_cast<__half2*>(&C[(size_t)row * N + col]) = h01;
                *reinterpret_cast<__half2*>(&C[(size_t)(row + 8) * N + col]) = h23;
            } else {
                *reinterpret_cast<float2*>(&Cf[(size_t)row * N + col]) = make_float2(v0, v1);
                *reinterpret_cast<float2*>(&Cf[(size_t)(row + 8) * N + col]) = make_float2(v2, v3);
            }
        }
    }
}

// ---------------- B/C projection + normalization (32-row tiles, 256 blocks) -----------
__global__ __launch_bounds__(256) void bc_kernel(const float* __restrict__ X,
                                                 const float* __restrict__ WB,
                                                 const float* __restrict__ WC) {
    __shared__ float Xs[32][65];
    __shared__ float Ws[32][65];
    const int tid = threadIdx.x;
    const int tx = tid & 31;        // n (0-15 -> B, 16-31 -> C)
    const int ty = tid >> 5;        // warp 0..7
    const int m0 = blockIdx.x * 32;

    float acc[4];
#pragma unroll
    for (int i = 0; i < 4; i++) acc[i] = 0.0f;

    for (int kt = 0; kt < CDMODEL; kt += 64) {
#pragma unroll
        for (int j = 0; j < 2; j++) {
            int q = tid + j * 256;            // 0..511 float4 quanta (32 rows x 16)
            int row = q >> 4;
            int c4 = (q & 15) * 4;
            float4 v = *reinterpret_cast<const float4*>(&X[(size_t)(m0 + row) * CDMODEL + kt + c4]);
            Xs[row][c4 + 0] = v.x; Xs[row][c4 + 1] = v.y;
            Xs[row][c4 + 2] = v.z; Xs[row][c4 + 3] = v.w;
        }
#pragma unroll
        for (int j = 0; j < 2; j++) {
            int q = tid + j * 256;
            int row = q >> 4;
            int c4 = (q & 15) * 4;
            const float* Wsrc = (row < 16) ? &WB[(size_t)row * CDMODEL]
                                           : &WC[(size_t)(row - 16) * CDMODEL];
            float4 v = *reinterpret_cast<const float4*>(&Wsrc[kt + c4]);
            Ws[row][c4 + 0] = v.x; Ws[row][c4 + 1] = v.y;
            Ws[row][c4 + 2] = v.z; Ws[row][c4 + 3] = v.w;
        }
        __syncthreads();
#pragma unroll 8
        for (int k = 0; k < 64; k++) {
            float wv = Ws[tx][k];
#pragma unroll
            for (int i = 0; i < 4; i++)
                acc[i] = fmaf(Xs[ty * 4 + i][k], wv, acc[i]);
        }
        __syncthreads();
    }

#pragma unroll
    for (int i = 0; i < 4; i++) {
        float v = acc[i];
        float ss = v * v;
#pragma unroll
        for (int off = 8; off >= 1; off >>= 1)
            ss += __shfl_xor_sync(0xffffffffu, ss, off);
        float sc = 1.0f / fmaxf(sqrtf(ss), 1.0f);
        v *= sc;
        int m = m0 + ty * 4 + i;
        if (tx < 16) g_Bn[(size_t)m * 16 + tx] = v;
        else         g_Cn[(size_t)m * 16 + (tx - 16)] = v;
    }
}

__device__ __forceinline__ bool check_fastA(const float* __restrict__ A_log, int d0) {
    int head = d0 / CHEADDIM;
    bool fast = true;
#pragma unroll
    for (int n = 0; n < 16; n++) {
        float a = expf(A_log[head * 16 + n]);
        if (fabsf(a - (float)(n + 1)) > 1e-3f * (float)(n + 1)) fast = false;
    }
    return fast;
}

__device__ __forceinline__ void load_Av(const float* __restrict__ A_log, int d, float* Av) {
    int head = d / CHEADDIM;
#pragma unroll
    for (int n = 0; n < 16; n++) Av[n] = expf(A_log[head * 16 + n]);
}

__device__ __forceinline__ void load16p(const float* p, ull_t* v) {   // 8 packed pairs
    const float4* q = reinterpret_cast<const float4*>(p);
    float4 a = q[0], b = q[1], c = q[2], d = q[3];
    v[0] = pk2(a.x, a.y); v[1] = pk2(a.z, a.w);
    v[2] = pk2(b.x, b.y); v[3] = pk2(b.z, b.w);
    v[4] = pk2(c.x, c.y); v[5] = pk2(c.z, c.w);
    v[6] = pk2(d.x, d.y); v[7] = pk2(d.z, d.w);
}

// packed scan step for one channel: hp[k] = p_k*hp[k] + dtx*Bp[k], p_k=(r^{2k+1},r^{2k+2})
__device__ __forceinline__ void scan_step(ull_t* hp, const ull_t* Bp, float r, float dtx) {
    float r2 = r * r;
    ull_t p = pk2(r, r2);
    ull_t r22 = pk2(r2, r2);
    ull_t dtx2 = pk2(dtx, dtx);
#pragma unroll
    for (int k = 0; k < 8; k++) {
        if (k > 0) p = mul2(p, r22);
        hp[k] = fma2(p, hp[k], mul2(Bp[k], dtx2));
    }
}

__device__ __forceinline__ void scan_step_gen(ull_t* hp, const ull_t* Bp, const ull_t* Avp,
                                              float dt, float dtx) {
    ull_t dtx2 = pk2(dtx, dtx);
#pragma unroll
    for (int k = 0; k < 8; k++) {
        float a0, a1;
        upk2(Avp[k], a0, a1);
        ull_t dec = pk2(__expf(-dt * a0), __expf(-dt * a1));
        hp[k] = fma2(dec, hp[k], mul2(Bp[k], dtx2));
    }
}

// ---------------- scan pass 1: channels d0=2i, d1=2i+1 ----------------
__global__ __launch_bounds__(256) void scan_pass1(const float* __restrict__ A_log) {
    int i = blockIdx.x * 256 + threadIdx.x;    // 0..1023
    int d0 = 2 * i;
    int c = blockIdx.y;
    int b = blockIdx.z;

    bool fastA = check_fastA(A_log, d0);
    ull_t Avp[8];
    if (!fastA) {
        float Av[16];
        load_Av(A_log, d0, Av);
#pragma unroll
        for (int k = 0; k < 8; k++) Avp[k] = pk2(Av[2 * k], Av[2 * k + 1]);
    }

    ull_t h0[8], h1[8];
    const ull_t z = pk2(0.0f, 0.0f);
#pragma unroll
    for (int k = 0; k < 8; k++) { h0[k] = z; h1[k] = z; }
    float S0 = 0.0f, S1 = 0.0f;

    int row0 = b * CSEQ + c * CLCHUNK;
    for (int t = 0; t < CLCHUNK; t++) {
        size_t ro = (size_t)(row0 + t) * CDMAMBA + d0;
        __half2 dtp = *reinterpret_cast<const __half2*>(&g_dt16[ro]);
        __half2 xp  = *reinterpret_cast<const __half2*>(&g_x16[ro]);
        float dt0 = __low2float(dtp), dt1 = __high2float(dtp);
        float x0 = __low2float(xp),   x1 = __high2float(xp);
        ull_t Bp[8];
        load16p(g_Bn + (size_t)(row0 + t) * 16, Bp);
        S0 += dt0; S1 += dt1;
        if (fastA) {
            scan_step(h0, Bp, __expf(-dt0), dt0 * x0);
            scan_step(h1, Bp, __expf(-dt1), dt1 * x1);
        } else {
            scan_step_gen(h0, Bp, Avp, dt0, dt0 * x0);
            scan_step_gen(h1, Bp, Avp, dt1, dt1 * x1);
        }
    }
    size_t base = ((size_t)(b * CNCHUNK + c) * 16) * CDMAMBA + d0;
#pragma unroll
    for (int k = 0; k < 8; k++) {
        float a0, a1, b0, b1;
        upk2(h0[k], a0, a1);   // n=2k, 2k+1 for channel d0
        upk2(h1[k], b0, b1);   // n=2k, 2k+1 for channel d0+1
        *reinterpret_cast<float2*>(&g_hloc[base + (size_t)(2 * k) * CDMAMBA]) = make_float2(a0, b0);
        *reinterpret_cast<float2*>(&g_hloc[base + (size_t)(2 * k + 1) * CDMAMBA]) = make_float2(a1, b1);
    }
    *reinterpret_cast<float2*>(&g_S[(size_t)(b * CNCHUNK + c) * CDMAMBA + d0]) = make_float2(S0, S1);
}

// ---------------- scan pass 2: one (b, n, d) chain per thread ----------------
__global__ __launch_bounds__(256) void scan_pass2(const float* __restrict__ A_log) {
    int idx = blockIdx.x * 256 + threadIdx.x;
    int d = idx % CDMAMBA;
    int bn = idx / CDMAMBA;
    int n = bn & 15;
    int b = bn >> 4;

    int head = d / CHEADDIM;
    float An = expf(A_log[head * 16 + n]);

    float h = 0.0f;
    for (int c = 0; c < CNCHUNK; c++) {
        size_t sidx = (size_t)(b * CNCHUNK + c) * CDMAMBA + d;
        size_t hidx = ((size_t)(b * CNCHUNK + c) * 16 + n) * CDMAMBA + d;
        g_hinit[hidx] = h;
        float S = g_S[sidx];
        h = fmaf(__expf(-S * An), h, g_hloc[hidx]);
    }
}

// ---------------- scan pass 3: channels d0=2i, d1=2i+1, emit y fp16 ----------------
__global__ __launch_bounds__(256) void scan_pass3(const float* __restrict__ A_log,
                                                  const float* __restrict__ Dvec) {
    int i = blockIdx.x * 256 + threadIdx.x;
    int d0 = 2 * i;
    int c = blockIdx.y;
    int b = blockIdx.z;

    bool fastA = check_fastA(A_log, d0);
    ull_t Avp[8];
    if (!fastA) {
        float Av[16];
        load_Av(A_log, d0, Av);
#pragma unroll
        for (int k = 0; k < 8; k++) Avp[k] = pk2(Av[2 * k], Av[2 * k + 1]);
    }
    float2 Dd = *reinterpret_cast<const float2*>(&Dvec[d0]);

    ull_t h0[8], h1[8];
    size_t base = ((size_t)(b * CNCHUNK + c) * 16) * CDMAMBA + d0;
#pragma unroll
    for (int k = 0; k < 8; k++) {
        float2 va = *reinterpret_cast<const float2*>(&g_hinit[base + (size_t)(2 * k) * CDMAMBA]);
        float2 vb = *reinterpret_cast<const float2*>(&g_hinit[base + (size_t)(2 * k + 1) * CDMAMBA]);
        h0[k] = pk2(va.x, vb.x);
        h1[k] = pk2(va.y, vb.y);
    }

    int row0 = b * CSEQ + c * CLCHUNK;
    for (int t = 0; t < CLCHUNK; t++) {
        size_t ro = (size_t)(row0 + t) * CDMAMBA + d0;
        __half2 dtp = *reinterpret_cast<const __half2*>(&g_dt16[ro]);
        __half2 xp  = *reinterpret_cast<const __half2*>(&g_x16[ro]);
        float dt0 = __low2float(dtp), dt1 = __high2float(dtp);
        float x0 = __low2float(xp),   x1 = __high2float(xp);
        ull_t Bp[8], Cp[8];
        load16p(g_Bn + (size_t)(row0 + t) * 16, Bp);
        load16p(g_Cn + (size_t)(row0 + t) * 16, Cp);
        if (fastA) {
            scan_step(h0, Bp, __expf(-dt0), dt0 * x0);
            scan_step(h1, Bp, __expf(-dt1), dt1 * x1);
        } else {
            scan_step_gen(h0, Bp, Avp, dt0, dt0 * x0);
            scan_step_gen(h1, Bp, Avp, dt1, dt1 * x1);
        }
        ull_t y0p = pk2(0.0f, 0.0f), y1p = pk2(0.0f, 0.0f);
#pragma unroll
        for (int k = 0; k < 8; k++) {
            y0p = fma2(h0[k], Cp[k], y0p);
            y1p = fma2(h1[k], Cp[k], y1p);
        }
        float ya, yb, yc, yd;
        upk2(y0p, ya, yb);
        upk2(y1p, yc, yd);
        float y0 = ya + yb, y1 = yc + yd;
        __half2 out = __halves2half2(__float2half(fmaf(x0, Dd.x, y0)),
                                     __float2half(fmaf(x1, Dd.y, y1)));
        *reinterpret_cast<__half2*>(&g_y_h[ro]) = out;
    }
}

// ---------------- launch ----------------
extern "C" void kernel_launch(void* const* d_in, const int* in_sizes, int n_in,
                              void* d_out, int out_size) {
    (void)in_sizes; (void)n_in; (void)out_size;
    const float* x_norm     = (const float*)d_in[0];
    const float* x_proj_w   = (const float*)d_in[1];
    const float* dt_proj_w  = (const float*)d_in[2];
    const float* dt_proj_b  = (const float*)d_in[3];
    const float* B_proj_w   = (const float*)d_in[4];
    const float* C_proj_w   = (const float*)d_in[5];
    const float* A_log      = (const float*)d_in[6];
    const float* Dvec       = (const float*)d_in[7];
    const float* out_proj_w = (const float*)d_in[8];
    float* out = (float*)d_out;

    void *p_xnh, *p_w1h, *p_w2h, *p_w3h, *p_yh, *p_x16, *p_dt16;
    cudaGetSymbolAddress(&p_xnh, g_xn_h);
    cudaGetSymbolAddress(&p_w1h, g_w1_h);
    cudaGetSymbolAddress(&p_w2h, g_w2_h);
    cudaGetSymbolAddress(&p_w3h, g_w3_h);
    cudaGetSymbolAddress(&p_yh, g_y_h);
    cudaGetSymbolAddress(&p_x16, g_x16);
    cudaGetSymbolAddress(&p_dt16, g_dt16);

    cudaFuncSetAttribute(gemm_mma<true>, cudaFuncAttributeMaxDynamicSharedMemorySize, SM_TOTAL);
    cudaFuncSetAttribute(gemm_mma<false>, cudaFuncAttributeMaxDynamicSharedMemorySize, SM_TOTAL);

    // fp16 conversions (launches 0-2)
    {
        int n4 = (CMROWS * CDMODEL) / 4;
        conv_h<<<n4 / 256, 256>>>(x_norm, (ushort_t*)p_xnh, n4);
        n4 = (CDMAMBA * CDMODEL) / 4;
        conv_h<<<n4 / 256, 256>>>(x_proj_w, (ushort_t*)p_w1h, n4);
        conv_h<<<n4 / 256, 256>>>(dt_proj_w, (ushort_t*)p_w2h, n4);
    }

    // normalized B, C (launch 3 — profiled slot)
    bc_kernel<<<CMROWS / 32, 256>>>(x_norm, B_proj_w, C_proj_w);

    // 1+2) fused GEMM
    {
        dim3 grid(2 * (CDMAMBA / 128), CMROWS / 128);   // (32, 64)
        gemm_mma<true><<<grid, 256, SM_TOTAL>>>(
            (const ushort_t*)p_xnh,
            (const ushort_t*)p_w1h, (const ushort_t*)p_w2h, dt_proj_b,
            (ushort_t*)p_x16, (ushort_t*)p_dt16, nullptr,
            CDMAMBA / 128, CDMAMBA, CDMODEL);
    }

    // W3 conversion
    {
        int n4 = (CDMAMBA * CDMAMBA) / 4;
        conv_h<<<n4 / 256, 256>>>(out_proj_w, (ushort_t*)p_w3h, n4);
    }

    // 4-6) chunked selective scan (packed f32x2 math)
    dim3 scan_grid((CDMAMBA / 2) / 256, CNCHUNK, CBATCH);   // (4, 32, 4)
    scan_pass1<<<scan_grid, 256>>>(A_log);
    scan_pass2<<<(CBATCH * 16 * CDMAMBA) / 256, 256>>>(A_log);   // 512 blocks
    scan_pass3<<<scan_grid, 256>>>(A_log, Dvec);

    // 7) out = y @ out_proj_w^T (fp32 output)
    {
        dim3 grid(CDMAMBA / 128, CMROWS / 128);   // (16, 64)
        gemm_mma<false><<<grid, 256, SM_TOTAL>>>(
            (const ushort_t*)p_yh,
            (const ushort_t*)p_w3h, (const ushort_t*)p_w3h, nullptr,
            nullptr, nullptr, out,
            CDMAMBA / 128, CDMAMBA, CDMAMBA);
    }
}

// round 13
// speedup vs baseline: 1.4395x; 1.0136x over previous
#include <cuda_runtime.h>
#include <cuda_fp16.h>
#include <math.h>
#include <stdint.h>

#define CBATCH   4
#define CSEQ     2048
#define CDMODEL  1024
#define CDMAMBA  2048
#define CDSTATE  16
#define CNHEADS  32
#define CMROWS   (CBATCH * CSEQ)          // 8192
#define CNCHUNK  32
#define CLCHUNK  (CSEQ / CNCHUNK)         // 64
#define CHEADDIM (CDMAMBA / CNHEADS)      // 64

typedef unsigned short ushort_t;
typedef unsigned long long ull_t;

// ---------------- scratch ----------------
__device__ float g_Bn  [CMROWS * CDSTATE];
__device__ float g_Cn  [CMROWS * CDSTATE];
__device__ float g_hloc [CBATCH * CNCHUNK * CDSTATE * CDMAMBA];
__device__ float g_hinit[CBATCH * CNCHUNK * CDSTATE * CDMAMBA];
__device__ float g_S    [CBATCH * CNCHUNK * CDMAMBA];

__device__ ushort_t g_xn_h[CMROWS * CDMODEL];
__device__ ushort_t g_w1_h[CDMAMBA * CDMODEL];
__device__ ushort_t g_w2_h[CDMAMBA * CDMODEL];
__device__ ushort_t g_w3_h[CDMAMBA * CDMAMBA];
__device__ ushort_t g_x16 [CMROWS * CDMAMBA];
__device__ ushort_t g_dt16[CMROWS * CDMAMBA];
__device__ ushort_t g_y_h [CMROWS * CDMAMBA];

// ---------------- PTX helpers ----------------
__device__ __forceinline__ uint32_t smem_u32(const void* p) {
    uint32_t a;
    asm("{ .reg .u64 t; cvta.to.shared.u64 t, %1; cvt.u32.u64 %0, t; }" : "=r"(a) : "l"(p));
    return a;
}

#define CP_ASYNC16(dst, src) \
    asm volatile("cp.async.cg.shared.global [%0], [%1], 16;" :: "r"(dst), "l"(src))
#define CP_COMMIT() asm volatile("cp.async.commit_group;" ::: "memory")
#define CP_WAIT0() asm volatile("cp.async.wait_group 0;" ::: "memory")
#define CP_WAIT1() asm volatile("cp.async.wait_group 1;" ::: "memory")

#define LDSM4(r, addr) \
    asm volatile("ldmatrix.sync.aligned.m8n8.x4.shared.b16 {%0,%1,%2,%3}, [%4];" \
        : "=r"((r)[0]), "=r"((r)[1]), "=r"((r)[2]), "=r"((r)[3]) : "r"(addr))

#define MMA_F16(d, a, b0, b1) \
    asm volatile("mma.sync.aligned.m16n8k16.row.col.f32.f16.f16.f32 " \
        "{%0,%1,%2,%3}, {%4,%5,%6,%7}, {%8,%9}, {%0,%1,%2,%3};" \
        : "+f"((d)[0]), "+f"((d)[1]), "+f"((d)[2]), "+f"((d)[3]) \
        : "r"((a)[0]), "r"((a)[1]), "r"((a)[2]), "r"((a)[3]), "r"(b0), "r"(b1))

__device__ __forceinline__ uint32_t swz(uint32_t off) {
    return off ^ ((off >> 3) & 0x70);
}

__device__ __forceinline__ ull_t pk2(float lo, float hi) {
    ull_t r; asm("mov.b64 %0, {%1, %2};" : "=l"(r) : "f"(lo), "f"(hi)); return r;
}
__device__ __forceinline__ void upk2(ull_t v, float& lo, float& hi) {
    asm("mov.b64 {%0, %1}, %2;" : "=f"(lo), "=f"(hi) : "l"(v));
}
__device__ __forceinline__ ull_t mul2(ull_t a, ull_t b) {
    ull_t r; asm("mul.rn.f32x2 %0, %1, %2;" : "=l"(r) : "l"(a), "l"(b)); return r;
}
__device__ __forceinline__ ull_t fma2(ull_t a, ull_t b, ull_t c) {
    ull_t r; asm("fma.rn.f32x2 %0, %1, %2, %3;" : "=l"(r) : "l"(a), "l"(b), "l"(c)); return r;
}

// ---------------- conversions ----------------
__device__ __forceinline__ void conv_one(const float* __restrict__ in,
                                         ushort_t* __restrict__ hi, int i) {
    float4 v = reinterpret_cast<const float4*>(in)[i];
    ushort4 h;
    h.x = __half_as_ushort(__float2half(v.x));
    h.y = __half_as_ushort(__float2half(v.y));
    h.z = __half_as_ushort(__float2half(v.z));
    h.w = __half_as_ushort(__float2half(v.w));
    reinterpret_cast<ushort4*>(hi)[i] = h;
}

// 3 input conversions in one launch: xn (2M quanta), w1 (512K), w2 (512K)
__global__ __launch_bounds__(256) void conv3(const float* __restrict__ xn, ushort_t* xh,
                                             const float* __restrict__ w1, ushort_t* w1h,
                                             const float* __restrict__ w2, ushort_t* w2h) {
    const int NA = (CMROWS * CDMODEL) / 4;        // 2M
    const int NB = (CDMAMBA * CDMODEL) / 4;       // 512K
    int id = blockIdx.x * 256 + threadIdx.x;
    if (id < NA)               conv_one(xn, xh, id);
    else if (id < NA + NB)     conv_one(w1, w1h, id - NA);
    else                       conv_one(w2, w2h, id - NA - NB);
}

__device__ __forceinline__ float dt_transform(float v, float b) {
    v += b;
    v = fminf(fmaxf(v, -10.0f), 5.0f);
    v = log1pf(expf(v));
    return fminf(fmaxf(v, 1e-4f), 0.1f);
}

// ---------------- GEMM building blocks (champion R8 geometry) ----------------
#define TILE_B   16384
#define STAGE_B  32768
#define SM_TOTAL (3 * STAGE_B)   // 98304

__device__ __forceinline__ void stage_load(
    const ushort_t* __restrict__ Ah, const ushort_t* __restrict__ Wh,
    uint32_t sbase, int m0, int n0, int kc, int K, int tid) {
#pragma unroll
    for (int tile = 0; tile < 2; tile++) {
        const ushort_t* g = (tile == 0) ? Ah : Wh;
        int row0 = (tile == 0) ? m0 : n0;
#pragma unroll
        for (int j = 0; j < 4; j++) {
            int idx = tid + j * 256;
            int row = idx >> 3, seg = idx & 7;
            const ushort_t* src = g + (size_t)(row0 + row) * K + kc + seg * 8;
            uint32_t dst = sbase + tile * TILE_B + swz((uint32_t)(row * 128 + seg * 16));
            CP_ASYNC16(dst, src);
        }
    }
}

__device__ __forceinline__ void ldsm_frags(uint32_t aA, uint32_t aW,
                                           int arow, int akb, int brow, int bkb,
                                           int kb, uint32_t ah[2][4], uint32_t bh[4][4]) {
#pragma unroll
    for (int mi = 0; mi < 2; mi++) {
        uint32_t off = swz((uint32_t)((arow + mi * 16) * 128 + akb + kb));
        LDSM4(ah[mi], aA + off);
    }
#pragma unroll
    for (int ni = 0; ni < 4; ni++) {
        uint32_t off = swz((uint32_t)((brow + ni * 16) * 128 + bkb + kb));
        LDSM4(bh[ni], aW + off);
    }
}

__device__ __forceinline__ void stage_compute(uint32_t sbase, int wm, int wn,
                                              int lane, float acc[2][8][4]) {
    const uint32_t aA = sbase;
    const uint32_t aW = sbase + TILE_B;
    const int arow = wm + (lane & 15);
    const int akb  = (lane >> 4) * 16;
    const int brow = wn + ((lane >> 4) << 3) + (lane & 7);
    const int bkb  = ((lane >> 3) & 1) * 16;

    uint32_t ah[2][2][4], bh[2][4][4];
    ldsm_frags(aA, aW, arow, akb, brow, bkb, 0, ah[0], bh[0]);

#pragma unroll
    for (int ks = 0; ks < 4; ks++) {
        const int cur = ks & 1;
        if (ks < 3)
            ldsm_frags(aA, aW, arow, akb, brow, bkb, (ks + 1) * 32,
                       ah[cur ^ 1], bh[cur ^ 1]);
#pragma unroll
        for (int mi = 0; mi < 2; mi++) {
#pragma unroll
            for (int ni = 0; ni < 4; ni++) {
                MMA_F16(acc[mi][2 * ni + 0], ah[cur][mi], bh[cur][ni][0], bh[cur][ni][1]);
                MMA_F16(acc[mi][2 * ni + 1], ah[cur][mi], bh[cur][ni][2], bh[cur][ni][3]);
            }
        }
    }
}

// GEMM body (shared by fused-front and GEMM3)
template <bool OUT16>
__device__ __forceinline__ void gemm_body(
    char* smem, const ushort_t* __restrict__ Ah, const ushort_t* __restrict__ Wh,
    bool second, const float* __restrict__ bias,
    ushort_t* __restrict__ C1h, ushort_t* __restrict__ C2h, float* __restrict__ Cf,
    int m0, int n0, int N, int K) {
    const uint32_t sb = smem_u32(smem);
    const int tid = threadIdx.x, lane = tid & 31, w = tid >> 5;
    const int wm = (w & 3) * 32, wn = (w >> 2) * 64;
    const int NC = K >> 6;

    float acc[2][8][4];
#pragma unroll
    for (int i = 0; i < 2; i++)
#pragma unroll
        for (int j = 0; j < 8; j++)
#pragma unroll
            for (int q = 0; q < 4; q++) acc[i][j][q] = 0.0f;

    stage_load(Ah, Wh, sb + 0 * STAGE_B, m0, n0, 0, K, tid);  CP_COMMIT();
    stage_load(Ah, Wh, sb + 1 * STAGE_B, m0, n0, 64, K, tid); CP_COMMIT();

    int sc = 0, sl = 2;
    for (int c = 0; c < NC; c++) {
        if (c + 1 < NC) { CP_WAIT1(); } else { CP_WAIT0(); }
        __syncthreads();
        if (c + 2 < NC) {
            stage_load(Ah, Wh, sb + sl * STAGE_B, m0, n0, (c + 2) * 64, K, tid);
            CP_COMMIT();
            sl = (sl == 2) ? 0 : sl + 1;
        }
        stage_compute(sb + sc * STAGE_B, wm, wn, lane, acc);
        sc = (sc == 2) ? 0 : sc + 1;
    }

    const int gm = m0 + wm, gn = n0 + wn;
    const int r = lane >> 2, cp = (lane & 3) * 2;
#pragma unroll
    for (int mi = 0; mi < 2; mi++) {
#pragma unroll
        for (int nj = 0; nj < 8; nj++) {
            int row = gm + mi * 16 + r;
            int col = gn + nj * 8 + cp;
            float v0 = acc[mi][nj][0], v1 = acc[mi][nj][1];
            float v2 = acc[mi][nj][2], v3 = acc[mi][nj][3];
            if (OUT16) {
                if (second) {
                    float2 bb = *reinterpret_cast<const float2*>(&bias[col]);
                    v0 = dt_transform(v0, bb.x);
                    v1 = dt_transform(v1, bb.y);
                    v2 = dt_transform(v2, bb.x);
                    v3 = dt_transform(v3, bb.y);
                }
                ushort_t* C = second ? C2h : C1h;
                __half2 h01 = __halves2half2(__float2half(v0), __float2half(v1));
                __half2 h23 = __halves2half2(__float2half(v2), __float2half(v3));
                *reinterpret_cast<__half2*>(&C[(size_t)row * N + col]) = h01;
                *reinterpret_cast<__half2*>(&C[(size_t)(row + 8) * N + col]) = h23;
            } else {
                *reinterpret_cast<float2*>(&Cf[(size_t)row * N + col]) = make_float2(v0, v1);
                *reinterpret_cast<float2*>(&Cf[(size_t)(row + 8) * N + col]) = make_float2(v2, v3);
            }
        }
    }
}

// bc block body (32 rows per block; uses dynamic smem)
__device__ __forceinline__ void bc_body(char* smem, int bid,
                                        const float* __restrict__ X,
                                        const float* __restrict__ WB,
                                        const float* __restrict__ WC) {
    float (*Xs)[65] = reinterpret_cast<float (*)[65]>(smem);
    float (*Ws)[65] = reinterpret_cast<float (*)[65]>(smem + 32 * 65 * sizeof(float));
    const int tid = threadIdx.x;
    const int tx = tid & 31;
    const int ty = tid >> 5;
    const int m0 = bid * 32;

    float acc[4];
#pragma unroll
    for (int i = 0; i < 4; i++) acc[i] = 0.0f;

    for (int kt = 0; kt < CDMODEL; kt += 64) {
#pragma unroll
        for (int j = 0; j < 2; j++) {
            int q = tid + j * 256;
            int row = q >> 4;
            int c4 = (q & 15) * 4;
            float4 v = *reinterpret_cast<const float4*>(&X[(size_t)(m0 + row) * CDMODEL + kt + c4]);
            Xs[row][c4 + 0] = v.x; Xs[row][c4 + 1] = v.y;
            Xs[row][c4 + 2] = v.z; Xs[row][c4 + 3] = v.w;
        }
#pragma unroll
        for (int j = 0; j < 2; j++) {
            int q = tid + j * 256;
            int row = q >> 4;
            int c4 = (q & 15) * 4;
            const float* Wsrc = (row < 16) ? &WB[(size_t)row * CDMODEL]
                                           : &WC[(size_t)(row - 16) * CDMODEL];
            float4 v = *reinterpret_cast<const float4*>(&Wsrc[kt + c4]);
            Ws[row][c4 + 0] = v.x; Ws[row][c4 + 1] = v.y;
            Ws[row][c4 + 2] = v.z; Ws[row][c4 + 3] = v.w;
        }
        __syncthreads();
#pragma unroll 8
        for (int k = 0; k < 64; k++) {
            float wv = Ws[tx][k];
#pragma unroll
            for (int i = 0; i < 4; i++)
                acc[i] = fmaf(Xs[ty * 4 + i][k], wv, acc[i]);
        }
        __syncthreads();
    }

#pragma unroll
    for (int i = 0; i < 4; i++) {
        float v = acc[i];
        float ss = v * v;
#pragma unroll
        for (int off = 8; off >= 1; off >>= 1)
            ss += __shfl_xor_sync(0xffffffffu, ss, off);
        float sc = 1.0f / fmaxf(sqrtf(ss), 1.0f);
        v *= sc;
        int m = m0 + ty * 4 + i;
        if (tx < 16) g_Bn[(size_t)m * 16 + tx] = v;
        else         g_Cn[(size_t)m * 16 + (tx - 16)] = v;
    }
}

// ---------------- FUSED FRONT: GEMM1+2 (bx<32) + bc (32<=bx<36) + conv_w3 (36<=bx<100)
// grid (100, 64), 256 threads, dynamic smem 96KB.
__global__ __launch_bounds__(256, 2) void fused_front(
    const ushort_t* __restrict__ Ah,
    const ushort_t* __restrict__ W1, const ushort_t* __restrict__ W2,
    const float* __restrict__ bias,
    ushort_t* __restrict__ C1h, ushort_t* __restrict__ C2h,
    const float* __restrict__ X, const float* __restrict__ WB, const float* __restrict__ WC,
    const float* __restrict__ w3src, ushort_t* __restrict__ w3h) {
    extern __shared__ __align__(1024) char smem[];
    const int bx = blockIdx.x, by = blockIdx.y;

    if (bx < 32) {
        const bool second = (bx >= 16);
        const int n0 = (second ? bx - 16 : bx) * 128;
        const int m0 = by * 128;
        gemm_body<true>(smem, Ah, second ? W2 : W1, second, bias,
                        C1h, C2h, nullptr, m0, n0, CDMAMBA, CDMODEL);
    } else if (bx < 36) {
        bc_body(smem, (bx - 32) * 64 + by, X, WB, WC);
    } else {
        int id = ((bx - 36) * 64 + by) * 256 + threadIdx.x;   // 0 .. 4096*256-1
        conv_one(w3src, w3h, id);                              // exactly 1M quanta
    }
}

// GEMM3 standalone (fp32 out)
__global__ __launch_bounds__(256, 2) void gemm_out(
    const ushort_t* __restrict__ Ah, const ushort_t* __restrict__ Wh,
    float* __restrict__ Cf, int N, int K) {
    extern __shared__ __align__(1024) char smem[];
    gemm_body<false>(smem, Ah, Wh, false, nullptr, nullptr, nullptr, Cf,
                     blockIdx.y * 128, blockIdx.x * 128, N, K);
}

// ---------------- scan helpers ----------------
__device__ __forceinline__ bool check_fastA(const float* __restrict__ A_log, int d0) {
    int head = d0 / CHEADDIM;
    bool fast = true;
#pragma unroll
    for (int n = 0; n < 16; n++) {
        float a = expf(A_log[head * 16 + n]);
        if (fabsf(a - (float)(n + 1)) > 1e-3f * (float)(n + 1)) fast = false;
    }
    return fast;
}

__device__ __forceinline__ void load_Av(const float* __restrict__ A_log, int d, float* Av) {
    int head = d / CHEADDIM;
#pragma unroll
    for (int n = 0; n < 16; n++) Av[n] = expf(A_log[head * 16 + n]);
}

__device__ __forceinline__ void load16p(const float* p, ull_t* v) {
    const float4* q = reinterpret_cast<const float4*>(p);
    float4 a = q[0], b = q[1], c = q[2], d = q[3];
    v[0] = pk2(a.x, a.y); v[1] = pk2(a.z, a.w);
    v[2] = pk2(b.x, b.y); v[3] = pk2(b.z, b.w);
    v[4] = pk2(c.x, c.y); v[5] = pk2(c.z, c.w);
    v[6] = pk2(d.x, d.y); v[7] = pk2(d.z, d.w);
}

__device__ __forceinline__ void scan_step(ull_t* hp, const ull_t* Bp, float r, float dtx) {
    float r2 = r * r;
    ull_t p = pk2(r, r2);
    ull_t r22 = pk2(r2, r2);
    ull_t dtx2 = pk2(dtx, dtx);
#pragma unroll
    for (int k = 0; k < 8; k++) {
        if (k > 0) p = mul2(p, r22);
        hp[k] = fma2(p, hp[k], mul2(Bp[k], dtx2));
    }
}

__device__ __forceinline__ void scan_step_gen(ull_t* hp, const ull_t* Bp, const ull_t* Avp,
                                              float dt, float dtx) {
    ull_t dtx2 = pk2(dtx, dtx);
#pragma unroll
    for (int k = 0; k < 8; k++) {
        float a0, a1;
        upk2(Avp[k], a0, a1);
        ull_t dec = pk2(__expf(-dt * a0), __expf(-dt * a1));
        hp[k] = fma2(dec, hp[k], mul2(Bp[k], dtx2));
    }
}

// ---------------- scan pass 1 ----------------
__global__ __launch_bounds__(256) void scan_pass1(const float* __restrict__ A_log) {
    int i = blockIdx.x * 256 + threadIdx.x;
    int d0 = 2 * i;
    int c = blockIdx.y;
    int b = blockIdx.z;

    bool fastA = check_fastA(A_log, d0);
    ull_t Avp[8];
    if (!fastA) {
        float Av[16];
        load_Av(A_log, d0, Av);
#pragma unroll
        for (int k = 0; k < 8; k++) Avp[k] = pk2(Av[2 * k], Av[2 * k + 1]);
    }

    ull_t h0[8], h1[8];
    const ull_t z = pk2(0.0f, 0.0f);
#pragma unroll
    for (int k = 0; k < 8; k++) { h0[k] = z; h1[k] = z; }
    float S0 = 0.0f, S1 = 0.0f;

    int row0 = b * CSEQ + c * CLCHUNK;
    for (int t = 0; t < CLCHUNK; t++) {
        size_t ro = (size_t)(row0 + t) * CDMAMBA + d0;
        __half2 dtp = *reinterpret_cast<const __half2*>(&g_dt16[ro]);
        __half2 xp  = *reinterpret_cast<const __half2*>(&g_x16[ro]);
        float dt0 = __low2float(dtp), dt1 = __high2float(dtp);
        float x0 = __low2float(xp),   x1 = __high2float(xp);
        ull_t Bp[8];
        load16p(g_Bn + (size_t)(row0 + t) * 16, Bp);
        S0 += dt0; S1 += dt1;
        if (fastA) {
            scan_step(h0, Bp, __expf(-dt0), dt0 * x0);
            scan_step(h1, Bp, __expf(-dt1), dt1 * x1);
        } else {
            scan_step_gen(h0, Bp, Avp, dt0, dt0 * x0);
            scan_step_gen(h1, Bp, Avp, dt1, dt1 * x1);
        }
    }
    size_t base = ((size_t)(b * CNCHUNK + c) * 16) * CDMAMBA + d0;
#pragma unroll
    for (int k = 0; k < 8; k++) {
        float a0, a1, b0, b1;
        upk2(h0[k], a0, a1);
        upk2(h1[k], b0, b1);
        *reinterpret_cast<float2*>(&g_hloc[base + (size_t)(2 * k) * CDMAMBA]) = make_float2(a0, b0);
        *reinterpret_cast<float2*>(&g_hloc[base + (size_t)(2 * k + 1) * CDMAMBA]) = make_float2(a1, b1);
    }
    *reinterpret_cast<float2*>(&g_S[(size_t)(b * CNCHUNK + c) * CDMAMBA + d0]) = make_float2(S0, S1);
}

// ---------------- scan pass 2 ----------------
__global__ __launch_bounds__(256) void scan_pass2(const float* __restrict__ A_log) {
    int idx = blockIdx.x * 256 + threadIdx.x;
    int d = idx % CDMAMBA;
    int bn = idx / CDMAMBA;
    int n = bn & 15;
    int b = bn >> 4;

    int head = d / CHEADDIM;
    float An = expf(A_log[head * 16 + n]);

    float h = 0.0f;
    for (int c = 0; c < CNCHUNK; c++) {
        size_t sidx = (size_t)(b * CNCHUNK + c) * CDMAMBA + d;
        size_t hidx = ((size_t)(b * CNCHUNK + c) * 16 + n) * CDMAMBA + d;
        g_hinit[hidx] = h;
        float S = g_S[sidx];
        h = fmaf(__expf(-S * An), h, g_hloc[hidx]);
    }
}

// ---------------- scan pass 3 ----------------
__global__ __launch_bounds__(256) void scan_pass3(const float* __restrict__ A_log,
                                                  const float* __restrict__ Dvec) {
    int i = blockIdx.x * 256 + threadIdx.x;
    int d0 = 2 * i;
    int c = blockIdx.y;
    int b = blockIdx.z;

    bool fastA = check_fastA(A_log, d0);
    ull_t Avp[8];
    if (!fastA) {
        float Av[16];
        load_Av(A_log, d0, Av);
#pragma unroll
        for (int k = 0; k < 8; k++) Avp[k] = pk2(Av[2 * k], Av[2 * k + 1]);
    }
    float2 Dd = *reinterpret_cast<const float2*>(&Dvec[d0]);

    ull_t h0[8], h1[8];
    size_t base = ((size_t)(b * CNCHUNK + c) * 16) * CDMAMBA + d0;
#pragma unroll
    for (int k = 0; k < 8; k++) {
        float2 va = *reinterpret_cast<const float2*>(&g_hinit[base + (size_t)(2 * k) * CDMAMBA]);
        float2 vb = *reinterpret_cast<const float2*>(&g_hinit[base + (size_t)(2 * k + 1) * CDMAMBA]);
        h0[k] = pk2(va.x, vb.x);
        h1[k] = pk2(va.y, vb.y);
    }

    int row0 = b * CSEQ + c * CLCHUNK;
    for (int t = 0; t < CLCHUNK; t++) {
        size_t ro = (size_t)(row0 + t) * CDMAMBA + d0;
        __half2 dtp = *reinterpret_cast<const __half2*>(&g_dt16[ro]);
        __half2 xp  = *reinterpret_cast<const __half2*>(&g_x16[ro]);
        float dt0 = __low2float(dtp), dt1 = __high2float(dtp);
        float x0 = __low2float(xp),   x1 = __high2float(xp);
        ull_t Bp[8], Cp[8];
        load16p(g_Bn + (size_t)(row0 + t) * 16, Bp);
        load16p(g_Cn + (size_t)(row0 + t) * 16, Cp);
        if (fastA) {
            scan_step(h0, Bp, __expf(-dt0), dt0 * x0);
            scan_step(h1, Bp, __expf(-dt1), dt1 * x1);
        } else {
            scan_step_gen(h0, Bp, Avp, dt0, dt0 * x0);
            scan_step_gen(h1, Bp, Avp, dt1, dt1 * x1);
        }
        ull_t y0p = pk2(0.0f, 0.0f), y1p = pk2(0.0f, 0.0f);
#pragma unroll
        for (int k = 0; k < 8; k++) {
            y0p = fma2(h0[k], Cp[k], y0p);
            y1p = fma2(h1[k], Cp[k], y1p);
        }
        float ya, yb, yc, yd;
        upk2(y0p, ya, yb);
        upk2(y1p, yc, yd);
        float y0 = ya + yb, y1 = yc + yd;
        __half2 out = __halves2half2(__float2half(fmaf(x0, Dd.x, y0)),
                                     __float2half(fmaf(x1, Dd.y, y1)));
        *reinterpret_cast<__half2*>(&g_y_h[ro]) = out;
    }
}

// ---------------- launch ----------------
extern "C" void kernel_launch(void* const* d_in, const int* in_sizes, int n_in,
                              void* d_out, int out_size) {
    (void)in_sizes; (void)n_in; (void)out_size;
    const float* x_norm     = (const float*)d_in[0];
    const float* x_proj_w   = (const float*)d_in[1];
    const float* dt_proj_w  = (const float*)d_in[2];
    const float* dt_proj_b  = (const float*)d_in[3];
    const float* B_proj_w   = (const float*)d_in[4];
    const float* C_proj_w   = (const float*)d_in[5];
    const float* A_log      = (const float*)d_in[6];
    const float* Dvec       = (const float*)d_in[7];
    const float* out_proj_w = (const float*)d_in[8];
    float* out = (float*)d_out;

    void *p_xnh, *p_w1h, *p_w2h, *p_w3h, *p_yh, *p_x16, *p_dt16;
    cudaGetSymbolAddress(&p_xnh, g_xn_h);
    cudaGetSymbolAddress(&p_w1h, g_w1_h);
    cudaGetSymbolAddress(&p_w2h, g_w2_h);
    cudaGetSymbolAddress(&p_w3h, g_w3_h);
    cudaGetSymbolAddress(&p_yh, g_y_h);
    cudaGetSymbolAddress(&p_x16, g_x16);
    cudaGetSymbolAddress(&p_dt16, g_dt16);

    cudaFuncSetAttribute(fused_front, cudaFuncAttributeMaxDynamicSharedMemorySize, SM_TOTAL);
    cudaFuncSetAttribute(gemm_out, cudaFuncAttributeMaxDynamicSharedMemorySize, SM_TOTAL);

    // input conversions (one launch): xn, w1, w2
    {
        int total = (CMROWS * CDMODEL + 2 * CDMAMBA * CDMODEL) / 4;   // 3M quanta
        conv3<<<total / 256, 256>>>(x_norm, (ushort_t*)p_xnh,
                                    x_proj_w, (ushort_t*)p_w1h,
                                    dt_proj_w, (ushort_t*)p_w2h);
    }

    // fused front: GEMM1+2 + bc + conv_w3 in one grid
    {
        dim3 grid(100, 64);
        fused_front<<<grid, 256, SM_TOTAL>>>(
            (const ushort_t*)p_xnh,
            (const ushort_t*)p_w1h, (const ushort_t*)p_w2h, dt_proj_b,
            (ushort_t*)p_x16, (ushort_t*)p_dt16,
            x_norm, B_proj_w, C_proj_w,
            out_proj_w, (ushort_t*)p_w3h);
    }

    // chunked selective scan
    dim3 scan_grid((CDMAMBA / 2) / 256, CNCHUNK, CBATCH);
    scan_pass1<<<scan_grid, 256>>>(A_log);
    scan_pass2<<<(CBATCH * 16 * CDMAMBA) / 256, 256>>>(A_log);
    scan_pass3<<<scan_grid, 256>>>(A_log, Dvec);

    // out = y @ out_proj_w^T (fp32)
    {
        dim3 grid(CDMAMBA / 128, CMROWS / 128);
        gemm_out<<<grid, 256, SM_TOTAL>>>(
            (const ushort_t*)p_yh, (const ushort_t*)p_w3h, out, CDMAMBA, CDMAMBA);
    }
}